// round 4
// baseline (speedup 1.0000x reference)
#include <cuda_runtime.h>
#include <cuda_bf16.h>
#include <cstdint>

// Problem constants
#define BB 4
#define TT 1024
#define CC 1024
#define HH 16
#define HS 64
#define LL 12
#define VV 50304
#define NN (BB*TT)          // 4096 tokens
#define FF (4*CC)           // 4096
#define C3 (3*CC)           // 3072

// ---------------- scratch (device globals; no allocation allowed) -----------
__device__ float g_x[NN*CC];
__device__ float g_h[NN*CC];
__device__ float g_qkv[(size_t)NN*C3];
__device__ float g_att[NN*CC];
__device__ float g_ffh[(size_t)NN*FF];
__device__ float g_S[(size_t)BB*HH*TT*TT];      // 268 MB attention scores
__device__ float g_rowloss[NN + 4];
__device__ float g_logits_fb[(size_t)NN*VV];    // fallback if d_out too small
// transposed weights [N,K] (tf32-rounded)
__device__ float g_WqkvT[(size_t)LL*C3*CC];     // rows: [Wq; Wk; Wv]
__device__ float g_WoT[(size_t)LL*CC*CC];
__device__ float g_W1T[(size_t)LL*CC*FF];
__device__ float g_W2T[(size_t)LL*FF*CC];
__device__ float g_WlmT[(size_t)CC*VV];

// ---------------- helpers ----------------------------------------------------
__device__ __forceinline__ uint32_t smem_u32(const void* p) {
    uint32_t a;
    asm("{ .reg .u64 t; cvta.to.shared.u64 t, %1; cvt.u32.u64 %0, t; }" : "=r"(a) : "l"(p));
    return a;
}
__device__ __forceinline__ float tf32r(float x) {
    uint32_t u; asm("cvt.rna.tf32.f32 %0, %1;" : "=r"(u) : "f"(x));
    return __uint_as_float(u);
}
__device__ __forceinline__ uint32_t swz(uint32_t b) { return b ^ ((b >> 3) & 0x70); }

__device__ __forceinline__ void cp16(void* s, const void* g) {
    uint32_t sa = smem_u32(s);
    asm volatile("cp.async.cg.shared.global [%0], [%1], 16;" :: "r"(sa), "l"(g));
}
#define CP_COMMIT() asm volatile("cp.async.commit_group;" ::: "memory")
#define CP_WAIT(n)  asm volatile("cp.async.wait_group %0;" :: "n"(n) : "memory")

__device__ __forceinline__ void mma_tf32(float* d, const uint32_t* a, const uint32_t* b) {
    asm volatile(
        "mma.sync.aligned.m16n8k8.row.col.f32.tf32.tf32.f32 "
        "{%0,%1,%2,%3}, {%4,%5,%6,%7}, {%8,%9}, {%0,%1,%2,%3};"
        : "+f"(d[0]), "+f"(d[1]), "+f"(d[2]), "+f"(d[3])
        : "r"(a[0]), "r"(a[1]), "r"(a[2]), "r"(a[3]), "r"(b[0]), "r"(b[1]));
}

// ---------------- reductions ------------------------------------------------
__device__ __forceinline__ float block_reduce_sum(float v, float* buf) {
    int tid = threadIdx.x;
    buf[tid] = v; __syncthreads();
    for (int s = 128; s > 0; s >>= 1) {
        if (tid < s) buf[tid] += buf[tid + s];
        __syncthreads();
    }
    float r = buf[0]; __syncthreads();
    return r;
}
__device__ __forceinline__ float block_reduce_max(float v, float* buf) {
    int tid = threadIdx.x;
    buf[tid] = v; __syncthreads();
    for (int s = 128; s > 0; s >>= 1) {
        if (tid < s) buf[tid] = fmaxf(buf[tid], buf[tid + s]);
        __syncthreads();
    }
    float r = buf[0]; __syncthreads();
    return r;
}

// ---------------- transpose: dst[N,K] = src[K,N], tf32-rounded ---------------
// separate z-strides so QKV sections can be packed into one [3C,K] matrix.
__global__ __launch_bounds__(256) void transpose_kernel(
    const float* __restrict__ src, float* __restrict__ dst, int K, int N,
    size_t src_zstride, size_t dst_zstride)
{
    __shared__ float t[32][33];
    const float* s = src + (size_t)blockIdx.z * src_zstride;
    float* d = dst + (size_t)blockIdx.z * dst_zstride;
    int n0 = blockIdx.x << 5, k0 = blockIdx.y << 5;
    int tx = threadIdx.x & 31, ty = threadIdx.x >> 5;
#pragma unroll
    for (int p = 0; p < 4; p++)
        t[ty + p * 8][tx] = s[(size_t)(k0 + ty + p * 8) * N + n0 + tx];
    __syncthreads();
#pragma unroll
    for (int p = 0; p < 4; p++)
        d[(size_t)(n0 + ty + p * 8) * K + k0 + tx] = tf32r(t[tx][ty + p * 8]);
}

// ---------------- embedding -------------------------------------------------
__global__ __launch_bounds__(256) void embed_kernel(
    const int* __restrict__ idx, const float* __restrict__ tok,
    const float* __restrict__ pos, float* __restrict__ x)
{
    size_t i = (size_t)blockIdx.x * 256 + threadIdx.x;
    int n = (int)(i >> 10);
    int c = (int)(i & 1023);
    int t = n & (TT - 1);
    x[i] = tok[(size_t)idx[n] * CC + c] + pos[(size_t)t * CC + c];
}

// ---------------- layernorm (tf32-rounded output: used only as GEMM A) ------
__global__ __launch_bounds__(256) void ln_kernel(
    const float* __restrict__ x, const float* __restrict__ g,
    const float* __restrict__ b, float* __restrict__ out)
{
    __shared__ float buf[256];
    int row = blockIdx.x;
    const float* xr = x + (size_t)row * CC;
    float s = 0.f, ss = 0.f;
    for (int c = threadIdx.x; c < CC; c += 256) {
        float v = xr[c]; s += v; ss += v * v;
    }
    s  = block_reduce_sum(s, buf);
    ss = block_reduce_sum(ss, buf);
    float mu  = s * (1.f / CC);
    float inv = rsqrtf(ss * (1.f / CC) - mu * mu + 1e-5f);
    float* orow = out + (size_t)row * CC;
    for (int c = threadIdx.x; c < CC; c += 256)
        orow[c] = tf32r((xr[c] - mu) * inv * g[c] + b[c]);
}

// ---------------- mma.sync tf32 GEMM: C = A[M,K] @ Bt[N,K]^T -----------------
// BM=128, BN=128, BK=32, 256 threads (8 warps, 2x4), 3-stage cp.async pipeline.
// 1-D grid with N-group swizzle (GW=16) for L2 reuse; 2 CTAs/SM.
#define GEMM_SMEM (3*32768)
#define GW 16
__global__ __launch_bounds__(256, 2) void mma_gemm_kernel(
    const float* __restrict__ A, const float* __restrict__ Bt,
    const float* __restrict__ bias, const float* __restrict__ res,
    float* __restrict__ C, int M, int N, int K, int relu)
{
    extern __shared__ char smem[];
    int tid = threadIdx.x;
    int wid = tid >> 5, lane = tid & 31;
    int g = lane >> 2, q = lane & 3;
    int wm0 = (wid >> 2) << 6;      // 0 or 64
    int wn0 = (wid & 3) << 5;       // 0,32,64,96

    int Mb = M >> 7, Nb = N >> 7;
    int bid = blockIdx.x;
    int group = bid / (Mb * GW);
    int rem = bid - group * Mb * GW;
    int gw = Nb - group * GW; if (gw > GW) gw = GW;
    int n_blk = group * GW + rem % gw;
    int m_blk = rem / gw;
    int m0 = m_blk << 7, n0 = n_blk << 7;

    const float* Abase = A + (size_t)m0 * K;
    const float* Bbase = Bt + (size_t)n0 * K;
    int Kc = K >> 5;

    float acc[4][4][4] = {};

    // prefetch stages 0,1
#pragma unroll
    for (int c = 0; c < 2; c++) {
        char* sa = smem + c * 32768;
        char* sbm = sa + 16384;
#pragma unroll
        for (int p = 0; p < 4; p++) {
            int id = p * 256 + tid;
            int row = id >> 3, ch = id & 7;
            uint32_t off = swz((row << 7) + (ch << 4));
            cp16(sa + off, Abase + (size_t)row * K + (c << 5) + (ch << 2));
            cp16(sbm + off, Bbase + (size_t)row * K + (c << 5) + (ch << 2));
        }
        CP_COMMIT();
    }

    for (int c = 0; c < Kc; c++) {
        if (c + 2 < Kc) { CP_WAIT(1); } else { CP_WAIT(0); }
        __syncthreads();
        if (c + 2 < Kc) {
            int cs = c + 2;
            char* sa = smem + (cs % 3) * 32768;
            char* sbm = sa + 16384;
#pragma unroll
            for (int p = 0; p < 4; p++) {
                int id = p * 256 + tid;
                int row = id >> 3, ch = id & 7;
                uint32_t off = swz((row << 7) + (ch << 4));
                cp16(sa + off, Abase + (size_t)row * K + (cs << 5) + (ch << 2));
                cp16(sbm + off, Bbase + (size_t)row * K + (cs << 5) + (ch << 2));
            }
            CP_COMMIT();
        }
        const char* As = smem + (c % 3) * 32768;
        const char* Bs = As + 16384;
#pragma unroll
        for (int ks = 0; ks < 4; ks++) {
            int k0 = ks << 3;
            uint32_t af[4][4];
#pragma unroll
            for (int mi = 0; mi < 4; mi++) {
                int r = wm0 + (mi << 4) + g;
                af[mi][0] = *(const uint32_t*)(As + swz((r << 7) + ((k0 + q) << 2)));
                af[mi][1] = *(const uint32_t*)(As + swz(((r + 8) << 7) + ((k0 + q) << 2)));
                af[mi][2] = *(const uint32_t*)(As + swz((r << 7) + ((k0 + q + 4) << 2)));
                af[mi][3] = *(const uint32_t*)(As + swz(((r + 8) << 7) + ((k0 + q + 4) << 2)));
            }
            uint32_t bf[4][2];
#pragma unroll
            for (int ni = 0; ni < 4; ni++) {
                int n = wn0 + (ni << 3) + g;
                bf[ni][0] = *(const uint32_t*)(Bs + swz((n << 7) + ((k0 + q) << 2)));
                bf[ni][1] = *(const uint32_t*)(Bs + swz((n << 7) + ((k0 + q + 4) << 2)));
            }
#pragma unroll
            for (int mi = 0; mi < 4; mi++)
#pragma unroll
                for (int ni = 0; ni < 4; ni++)
                    mma_tf32(acc[mi][ni], af[mi], bf[ni]);
        }
    }

    // epilogue
#pragma unroll
    for (int mi = 0; mi < 4; mi++) {
#pragma unroll
        for (int half = 0; half < 2; half++) {
            int row = m0 + wm0 + (mi << 4) + g + half * 8;
            float* crow = C + (size_t)row * N;
            const float* rrow = res ? res + (size_t)row * N : nullptr;
#pragma unroll
            for (int ni = 0; ni < 4; ni++) {
                int col = n0 + wn0 + (ni << 3) + (q << 1);
                float v0 = acc[mi][ni][half * 2 + 0];
                float v1 = acc[mi][ni][half * 2 + 1];
                if (bias) { v0 += bias[col]; v1 += bias[col + 1]; }
                if (relu) {
                    v0 = tf32r(fmaxf(v0, 0.f));
                    v1 = tf32r(fmaxf(v1, 0.f));
                }
                if (rrow) { v0 += rrow[col]; v1 += rrow[col + 1]; }
                float2 o; o.x = v0; o.y = v1;
                *(float2*)(crow + col) = o;
            }
        }
    }
}

// ---------------- attention: S = scale * Q @ K^T (reads fused qkv) ----------
__global__ __launch_bounds__(256) void attn_scores(
    const float* __restrict__ qkv, float* __restrict__ S)
{
    int jt = blockIdx.x, it = blockIdx.y, bh = blockIdx.z;
    if (jt > it) return;
    int b = bh >> 4, h = bh & 15;
    const float* Qb = qkv + ((size_t)b * TT + (size_t)it * 64) * C3 + h * 64;
    const float* Kb = qkv + ((size_t)b * TT + (size_t)jt * 64) * C3 + CC + h * 64;
    __shared__ float Qs[64][65];
    __shared__ float Ks[64][65];
    int tid = threadIdx.x;
#pragma unroll
    for (int p = 0; p < 4; p++) {
        int id4 = p * 256 + tid;
        int r = id4 >> 4;
        int c4 = (id4 & 15) << 2;
        float4 qv = *(const float4*)(Qb + (size_t)r * C3 + c4);
        Qs[r][c4] = qv.x; Qs[r][c4+1] = qv.y; Qs[r][c4+2] = qv.z; Qs[r][c4+3] = qv.w;
        float4 kv = *(const float4*)(Kb + (size_t)r * C3 + c4);
        Ks[r][c4] = kv.x; Ks[r][c4+1] = kv.y; Ks[r][c4+2] = kv.z; Ks[r][c4+3] = kv.w;
    }
    __syncthreads();
    int ty = tid >> 4, tx = tid & 15;
    float acc[4][4] = {};
#pragma unroll 4
    for (int d = 0; d < 64; d++) {
        float a[4], bb[4];
#pragma unroll
        for (int i = 0; i < 4; i++) a[i]  = Qs[(ty << 2) + i][d];
#pragma unroll
        for (int j = 0; j < 4; j++) bb[j] = Ks[(tx << 2) + j][d];
#pragma unroll
        for (int i = 0; i < 4; i++)
#pragma unroll
            for (int j = 0; j < 4; j++)
                acc[i][j] = fmaf(a[i], bb[j], acc[i][j]);
    }
    float* Sp = S + (size_t)bh * TT * TT;
#pragma unroll
    for (int i = 0; i < 4; i++) {
        int row = it * 64 + (ty << 2) + i;
#pragma unroll
        for (int j = 0; j < 4; j++)
            Sp[(size_t)row * TT + jt * 64 + (tx << 2) + j] = acc[i][j] * 0.125f;
    }
}

// ---------------- causal softmax over rows of S ------------------------------
__global__ __launch_bounds__(256) void attn_softmax(float* __restrict__ S)
{
    __shared__ float buf[256];
    int i = blockIdx.x, bh = blockIdx.y;
    float* row = S + (size_t)bh * TT * TT + (size_t)i * TT;
    int len = i + 1;
    float m = -3.4e38f;
    for (int j = threadIdx.x; j < len; j += 256) m = fmaxf(m, row[j]);
    m = block_reduce_max(m, buf);
    float s = 0.f;
    for (int j = threadIdx.x; j < len; j += 256) {
        float e = __expf(row[j] - m);
        row[j] = e; s += e;
    }
    s = block_reduce_sum(s, buf);
    float inv = 1.f / s;
    for (int j = threadIdx.x; j < len; j += 256) row[j] *= inv;
    int lim = ((i >> 6) + 1) << 6;
    for (int j = len + threadIdx.x; j < lim; j += 256) row[j] = 0.f;
}

// ---------------- O = P @ V (att output tf32-rounded: GEMM A input) ----------
__global__ __launch_bounds__(256) void attn_pv(
    const float* __restrict__ S, const float* __restrict__ qkv,
    float* __restrict__ o)
{
    int it = blockIdx.x, bh = blockIdx.y;
    int b = bh >> 4, h = bh & 15;
    const float* P  = S + (size_t)bh * TT * TT + (size_t)it * 64 * TT;
    const float* Vb = qkv + (size_t)b * TT * C3 + 2 * CC + h * 64;
    float* Ob = o + ((size_t)b * TT + (size_t)it * 64) * CC + h * 64;
    __shared__ float Ps[64][17];
    __shared__ float Vs[16][64];
    int tid = threadIdx.x, ty = tid >> 4, tx = tid & 15;
    float acc[4][4] = {};
    int kend = (it + 1) * 64;
    int pr = tid >> 2,  pc4 = (tid & 3) << 2;
    int vr = tid >> 4,  vc4 = (tid & 15) << 2;
    for (int k0 = 0; k0 < kend; k0 += 16) {
        float4 pv = *(const float4*)(P + (size_t)pr * TT + k0 + pc4);
        Ps[pr][pc4] = pv.x; Ps[pr][pc4+1] = pv.y; Ps[pr][pc4+2] = pv.z; Ps[pr][pc4+3] = pv.w;
        *(float4*)&Vs[vr][vc4] = *(const float4*)(Vb + (size_t)(k0 + vr) * C3 + vc4);
        __syncthreads();
#pragma unroll
        for (int kk = 0; kk < 16; kk++) {
            float a[4], bb[4];
#pragma unroll
            for (int i = 0; i < 4; i++) a[i]  = Ps[(ty << 2) + i][kk];
#pragma unroll
            for (int j = 0; j < 4; j++) bb[j] = Vs[kk][(tx << 2) + j];
#pragma unroll
            for (int i = 0; i < 4; i++)
#pragma unroll
                for (int j = 0; j < 4; j++)
                    acc[i][j] = fmaf(a[i], bb[j], acc[i][j]);
        }
        __syncthreads();
    }
#pragma unroll
    for (int i = 0; i < 4; i++)
#pragma unroll
        for (int j = 0; j < 4; j++)
            Ob[(size_t)((ty << 2) + i) * CC + (tx << 2) + j] = tf32r(acc[i][j]);
}

// ---------------- loss -------------------------------------------------------
__global__ __launch_bounds__(256) void row_loss_kernel(
    const float* __restrict__ logits, const int* __restrict__ targets,
    float* __restrict__ rl)
{
    __shared__ float buf[256];
    int row = blockIdx.x;
    const float* lr = logits + (size_t)row * VV;
    float m = -3.4e38f;
    for (int j = threadIdx.x; j < VV; j += 256) m = fmaxf(m, lr[j]);
    m = block_reduce_max(m, buf);
    float s = 0.f;
    for (int j = threadIdx.x; j < VV; j += 256) s += __expf(lr[j] - m);
    s = block_reduce_sum(s, buf);
    if (threadIdx.x == 0) {
        int t = targets[row];
        rl[row] = -(lr[t] - m - logf(s));
    }
}

__global__ __launch_bounds__(256) void loss_reduce_kernel(
    const float* __restrict__ rl, float* __restrict__ out)
{
    __shared__ float buf[256];
    float s = 0.f;
    for (int i = threadIdx.x; i < NN; i += 256) s += rl[i];
    s = block_reduce_sum(s, buf);
    if (threadIdx.x == 0) out[0] = s * (1.f / NN);
}

// ---------------- host orchestration ----------------------------------------
static inline void run_gemm(const float* A, const float* Wt, const float* bias,
                            const float* res, float* C, int M, int N, int K, int relu)
{
    int grid = (M / 128) * (N / 128);
    mma_gemm_kernel<<<grid, 256, GEMM_SMEM>>>(A, Wt, bias, res, C, M, N, K, relu);
}

extern "C" void kernel_launch(void* const* d_in, const int* in_sizes, int n_in,
                              void* d_out, int out_size)
{
    const int*   idx     = (const int*)  d_in[0];
    const int*   targets = (const int*)  d_in[1];
    const float* tok     = (const float*)d_in[2];
    const float* pos     = (const float*)d_in[3];
    const float* ln1_g   = (const float*)d_in[4];
    const float* ln1_b   = (const float*)d_in[5];
    const float* Wq      = (const float*)d_in[6];
    const float* Wk      = (const float*)d_in[7];
    const float* Wv      = (const float*)d_in[8];
    const float* Wo      = (const float*)d_in[9];
    const float* bo      = (const float*)d_in[10];
    const float* ln2_g   = (const float*)d_in[11];
    const float* ln2_b   = (const float*)d_in[12];
    const float* W1      = (const float*)d_in[13];
    const float* b1      = (const float*)d_in[14];
    const float* W2      = (const float*)d_in[15];
    const float* b2      = (const float*)d_in[16];
    const float* lnf_g   = (const float*)d_in[17];
    const float* lnf_b   = (const float*)d_in[18];
    const float* Wlm     = (const float*)d_in[19];
    const float* blm     = (const float*)d_in[20];
    (void)in_sizes; (void)n_in;

    cudaFuncSetAttribute(mma_gemm_kernel,
                         cudaFuncAttributeMaxDynamicSharedMemorySize, GEMM_SMEM);

    void* p;
    cudaGetSymbolAddress(&p, g_x);      float* x    = (float*)p;
    cudaGetSymbolAddress(&p, g_h);      float* h    = (float*)p;
    cudaGetSymbolAddress(&p, g_qkv);    float* qkv  = (float*)p;
    cudaGetSymbolAddress(&p, g_att);    float* att  = (float*)p;
    cudaGetSymbolAddress(&p, g_ffh);    float* ffh  = (float*)p;
    cudaGetSymbolAddress(&p, g_S);      float* S    = (float*)p;
    cudaGetSymbolAddress(&p, g_rowloss);float* rl   = (float*)p;
    cudaGetSymbolAddress(&p, g_logits_fb); float* logits_fb = (float*)p;
    cudaGetSymbolAddress(&p, g_WqkvT);  float* WqkvT = (float*)p;
    cudaGetSymbolAddress(&p, g_WoT);    float* WoT  = (float*)p;
    cudaGetSymbolAddress(&p, g_W1T);    float* W1T  = (float*)p;
    cudaGetSymbolAddress(&p, g_W2T);    float* W2T  = (float*)p;
    cudaGetSymbolAddress(&p, g_WlmT);   float* WlmT = (float*)p;

    const size_t NV = (size_t)NN * VV;
    float* out = (float*)d_out;
    bool big = ((size_t)out_size >= NV);
    float* logits   = big ? out : logits_fb;
    float* loss_dst = ((size_t)out_size > NV) ? out + NV
                    : (big ? rl + NN : out);

    // transpose all weights to [N,K] (tf32-rounded); QKV packed as [3C,K]
    transpose_kernel<<<dim3(CC/32, CC/32, LL), 256>>>(Wq, WqkvT + 0 * (size_t)CC * CC,
        CC, CC, (size_t)CC * CC, (size_t)C3 * CC);
    transpose_kernel<<<dim3(CC/32, CC/32, LL), 256>>>(Wk, WqkvT + 1 * (size_t)CC * CC,
        CC, CC, (size_t)CC * CC, (size_t)C3 * CC);
    transpose_kernel<<<dim3(CC/32, CC/32, LL), 256>>>(Wv, WqkvT + 2 * (size_t)CC * CC,
        CC, CC, (size_t)CC * CC, (size_t)C3 * CC);
    transpose_kernel<<<dim3(CC/32, CC/32, LL), 256>>>(Wo, WoT, CC, CC,
        (size_t)CC * CC, (size_t)CC * CC);
    transpose_kernel<<<dim3(FF/32, CC/32, LL), 256>>>(W1, W1T, CC, FF,
        (size_t)CC * FF, (size_t)CC * FF);
    transpose_kernel<<<dim3(CC/32, FF/32, LL), 256>>>(W2, W2T, FF, CC,
        (size_t)FF * CC, (size_t)FF * CC);
    transpose_kernel<<<dim3(VV/32, CC/32, 1),  256>>>(Wlm, WlmT, CC, VV, 0, 0);

    // embedding
    embed_kernel<<<(NN * CC) / 256, 256>>>(idx, tok, pos, x);

    for (int l = 0; l < LL; l++) {
        const size_t oC  = (size_t)l * CC;
        const size_t oCC = (size_t)l * CC * CC;
        const size_t oCF = (size_t)l * CC * FF;
        const size_t oF  = (size_t)l * FF;
        const size_t oQ  = (size_t)l * C3 * CC;

        ln_kernel<<<NN, 256>>>(x, ln1_g + oC, ln1_b + oC, h);
        run_gemm(h, WqkvT + oQ, nullptr, nullptr, qkv, NN, C3, CC, 0);

        attn_scores<<<dim3(TT / 64, TT / 64, BB * HH), 256>>>(qkv, S);
        attn_softmax<<<dim3(TT, BB * HH), 256>>>(S);
        attn_pv<<<dim3(TT / 64, BB * HH), 256>>>(S, qkv, att);

        run_gemm(att, WoT + oCC, bo + oC, x, x, NN, CC, CC, 0);

        ln_kernel<<<NN, 256>>>(x, ln2_g + oC, ln2_b + oC, h);
        run_gemm(h, W1T + oCF, b1 + oF, nullptr, ffh, NN, FF, CC, 1);
        run_gemm(ffh, W2T + oCF, b2 + oC, x, x, NN, CC, FF, 0);
    }

    ln_kernel<<<NN, 256>>>(x, lnf_g, lnf_b, h);
    run_gemm(h, WlmT, blm, nullptr, logits, NN, VV, CC, 0);

    row_loss_kernel<<<NN, 256>>>(logits, targets, rl);
    loss_reduce_kernel<<<1, 256>>>(rl, loss_dst);
}

// round 5
// speedup vs baseline: 1.2580x; 1.2580x over previous
#include <cuda_runtime.h>
#include <cuda_bf16.h>
#include <cstdint>

// Problem constants
#define BB 4
#define TT 1024
#define CC 1024
#define HH 16
#define HS 64
#define LL 12
#define VV 50304
#define NN (BB*TT)          // 4096 tokens
#define FF (4*CC)           // 4096
#define C3 (3*CC)           // 3072

// ---------------- scratch (device globals; no allocation allowed) -----------
__device__ float g_x[NN*CC];
__device__ float g_h[NN*CC];
__device__ float g_qkv[(size_t)NN*C3];
__device__ float g_att[NN*CC];
__device__ float g_ffh[(size_t)NN*FF];
__device__ float g_S[(size_t)BB*HH*TT*TT];      // 268 MB attention scores
__device__ float g_rowloss[NN + 4];
__device__ float g_logits_fb[(size_t)NN*VV];    // fallback if d_out too small
// transposed weights [N,K] (tf32-rounded)
__device__ float g_WqkvT[(size_t)LL*C3*CC];     // rows: [Wq; Wk; Wv]
__device__ float g_WoT[(size_t)LL*CC*CC];
__device__ float g_W1T[(size_t)LL*CC*FF];
__device__ float g_W2T[(size_t)LL*FF*CC];
__device__ float g_WlmT[(size_t)CC*VV];

// ---------------- helpers ----------------------------------------------------
__device__ __forceinline__ uint32_t smem_u32(const void* p) {
    uint32_t a;
    asm("{ .reg .u64 t; cvta.to.shared.u64 t, %1; cvt.u32.u64 %0, t; }" : "=r"(a) : "l"(p));
    return a;
}
__device__ __forceinline__ float tf32r(float x) {
    uint32_t u; asm("cvt.rna.tf32.f32 %0, %1;" : "=r"(u) : "f"(x));
    return __uint_as_float(u);
}
__device__ __forceinline__ uint32_t swz(uint32_t b) { return b ^ ((b >> 3) & 0x70); }

__device__ __forceinline__ void cp16(void* s, const void* g) {
    uint32_t sa = smem_u32(s);
    asm volatile("cp.async.cg.shared.global [%0], [%1], 16;" :: "r"(sa), "l"(g));
}
#define CP_COMMIT() asm volatile("cp.async.commit_group;" ::: "memory")
#define CP_WAIT(n)  asm volatile("cp.async.wait_group %0;" :: "n"(n) : "memory")

__device__ __forceinline__ void mma_tf32(float* d, const uint32_t* a, const uint32_t* b) {
    asm volatile(
        "mma.sync.aligned.m16n8k8.row.col.f32.tf32.tf32.f32 "
        "{%0,%1,%2,%3}, {%4,%5,%6,%7}, {%8,%9}, {%0,%1,%2,%3};"
        : "+f"(d[0]), "+f"(d[1]), "+f"(d[2]), "+f"(d[3])
        : "r"(a[0]), "r"(a[1]), "r"(a[2]), "r"(a[3]), "r"(b[0]), "r"(b[1]));
}

// ---------------- reductions ------------------------------------------------
__device__ __forceinline__ float block_reduce_sum(float v, float* buf) {
    int tid = threadIdx.x;
    buf[tid] = v; __syncthreads();
    for (int s = 128; s > 0; s >>= 1) {
        if (tid < s) buf[tid] += buf[tid + s];
        __syncthreads();
    }
    float r = buf[0]; __syncthreads();
    return r;
}
__device__ __forceinline__ float block_reduce_max(float v, float* buf) {
    int tid = threadIdx.x;
    buf[tid] = v; __syncthreads();
    for (int s = 128; s > 0; s >>= 1) {
        if (tid < s) buf[tid] = fmaxf(buf[tid], buf[tid + s]);
        __syncthreads();
    }
    float r = buf[0]; __syncthreads();
    return r;
}

// ---------------- transpose: dst[N,K] = src[K,N], tf32-rounded ---------------
// separate z-strides so QKV sections can be packed into one [3C,K] matrix.
__global__ __launch_bounds__(256) void transpose_kernel(
    const float* __restrict__ src, float* __restrict__ dst, int K, int N,
    size_t src_zstride, size_t dst_zstride)
{
    __shared__ float t[32][33];
    const float* s = src + (size_t)blockIdx.z * src_zstride;
    float* d = dst + (size_t)blockIdx.z * dst_zstride;
    int n0 = blockIdx.x << 5, k0 = blockIdx.y << 5;
    int tx = threadIdx.x & 31, ty = threadIdx.x >> 5;
#pragma unroll
    for (int p = 0; p < 4; p++)
        t[ty + p * 8][tx] = s[(size_t)(k0 + ty + p * 8) * N + n0 + tx];
    __syncthreads();
#pragma unroll
    for (int p = 0; p < 4; p++)
        d[(size_t)(n0 + ty + p * 8) * K + k0 + tx] = tf32r(t[tx][ty + p * 8]);
}

// ---------------- embedding -------------------------------------------------
__global__ __launch_bounds__(256) void embed_kernel(
    const int* __restrict__ idx, const float* __restrict__ tok,
    const float* __restrict__ pos, float* __restrict__ x)
{
    size_t i = (size_t)blockIdx.x * 256 + threadIdx.x;
    int n = (int)(i >> 10);
    int c = (int)(i & 1023);
    int t = n & (TT - 1);
    x[i] = tok[(size_t)idx[n] * CC + c] + pos[(size_t)t * CC + c];
}

// ---------------- layernorm (tf32-rounded output: used only as GEMM A) ------
__global__ __launch_bounds__(256) void ln_kernel(
    const float* __restrict__ x, const float* __restrict__ g,
    const float* __restrict__ b, float* __restrict__ out)
{
    __shared__ float buf[256];
    int row = blockIdx.x;
    const float* xr = x + (size_t)row * CC;
    float s = 0.f, ss = 0.f;
    for (int c = threadIdx.x; c < CC; c += 256) {
        float v = xr[c]; s += v; ss += v * v;
    }
    s  = block_reduce_sum(s, buf);
    ss = block_reduce_sum(ss, buf);
    float mu  = s * (1.f / CC);
    float inv = rsqrtf(ss * (1.f / CC) - mu * mu + 1e-5f);
    float* orow = out + (size_t)row * CC;
    for (int c = threadIdx.x; c < CC; c += 256)
        orow[c] = tf32r((xr[c] - mu) * inv * g[c] + b[c]);
}

// ---------------- mma.sync tf32 GEMM: C = A[M,K] @ Bt[N,K]^T -----------------
// BM=128, BN=128, BK=32, 256 threads (8 warps, 2x4), 3-stage cp.async pipeline.
// 1-D grid with N-group swizzle (GW=16) for L2 reuse. Full register budget:
// this kernel is register-limited to 1 CTA/SM — do NOT cap regs (R4 lesson).
#define GEMM_SMEM (3*32768)
#define GW 16
__global__ __launch_bounds__(256) void mma_gemm_kernel(
    const float* __restrict__ A, const float* __restrict__ Bt,
    const float* __restrict__ bias, const float* __restrict__ res,
    float* __restrict__ C, int M, int N, int K, int relu)
{
    extern __shared__ char smem[];
    int tid = threadIdx.x;
    int wid = tid >> 5, lane = tid & 31;
    int g = lane >> 2, q = lane & 3;
    int wm0 = (wid >> 2) << 6;      // 0 or 64
    int wn0 = (wid & 3) << 5;       // 0,32,64,96

    int Mb = M >> 7, Nb = N >> 7;
    int bid = blockIdx.x;
    int group = bid / (Mb * GW);
    int rem = bid - group * Mb * GW;
    int gw = Nb - group * GW; if (gw > GW) gw = GW;
    int n_blk = group * GW + rem % gw;
    int m_blk = rem / gw;
    int m0 = m_blk << 7, n0 = n_blk << 7;

    const float* Abase = A + (size_t)m0 * K;
    const float* Bbase = Bt + (size_t)n0 * K;
    int Kc = K >> 5;

    float acc[4][4][4] = {};

    // prefetch stages 0,1
#pragma unroll
    for (int c = 0; c < 2; c++) {
        char* sa = smem + c * 32768;
        char* sbm = sa + 16384;
#pragma unroll
        for (int p = 0; p < 4; p++) {
            int id = p * 256 + tid;
            int row = id >> 3, ch = id & 7;
            uint32_t off = swz((row << 7) + (ch << 4));
            cp16(sa + off, Abase + (size_t)row * K + (c << 5) + (ch << 2));
            cp16(sbm + off, Bbase + (size_t)row * K + (c << 5) + (ch << 2));
        }
        CP_COMMIT();
    }

    for (int c = 0; c < Kc; c++) {
        if (c + 2 < Kc) { CP_WAIT(1); } else { CP_WAIT(0); }
        __syncthreads();
        if (c + 2 < Kc) {
            int cs = c + 2;
            char* sa = smem + (cs % 3) * 32768;
            char* sbm = sa + 16384;
#pragma unroll
            for (int p = 0; p < 4; p++) {
                int id = p * 256 + tid;
                int row = id >> 3, ch = id & 7;
                uint32_t off = swz((row << 7) + (ch << 4));
                cp16(sa + off, Abase + (size_t)row * K + (cs << 5) + (ch << 2));
                cp16(sbm + off, Bbase + (size_t)row * K + (cs << 5) + (ch << 2));
            }
            CP_COMMIT();
        }
        const char* As = smem + (c % 3) * 32768;
        const char* Bs = As + 16384;
#pragma unroll
        for (int ks = 0; ks < 4; ks++) {
            int k0 = ks << 3;
            uint32_t af[4][4];
#pragma unroll
            for (int mi = 0; mi < 4; mi++) {
                int r = wm0 + (mi << 4) + g;
                af[mi][0] = *(const uint32_t*)(As + swz((r << 7) + ((k0 + q) << 2)));
                af[mi][1] = *(const uint32_t*)(As + swz(((r + 8) << 7) + ((k0 + q) << 2)));
                af[mi][2] = *(const uint32_t*)(As + swz((r << 7) + ((k0 + q + 4) << 2)));
                af[mi][3] = *(const uint32_t*)(As + swz(((r + 8) << 7) + ((k0 + q + 4) << 2)));
            }
            uint32_t bf[4][2];
#pragma unroll
            for (int ni = 0; ni < 4; ni++) {
                int n = wn0 + (ni << 3) + g;
                bf[ni][0] = *(const uint32_t*)(Bs + swz((n << 7) + ((k0 + q) << 2)));
                bf[ni][1] = *(const uint32_t*)(Bs + swz((n << 7) + ((k0 + q + 4) << 2)));
            }
#pragma unroll
            for (int mi = 0; mi < 4; mi++)
#pragma unroll
                for (int ni = 0; ni < 4; ni++)
                    mma_tf32(acc[mi][ni], af[mi], bf[ni]);
        }
    }

    // epilogue
#pragma unroll
    for (int mi = 0; mi < 4; mi++) {
#pragma unroll
        for (int half = 0; half < 2; half++) {
            int row = m0 + wm0 + (mi << 4) + g + half * 8;
            float* crow = C + (size_t)row * N;
            const float* rrow = res ? res + (size_t)row * N : nullptr;
#pragma unroll
            for (int ni = 0; ni < 4; ni++) {
                int col = n0 + wn0 + (ni << 3) + (q << 1);
                float v0 = acc[mi][ni][half * 2 + 0];
                float v1 = acc[mi][ni][half * 2 + 1];
                if (bias) { v0 += bias[col]; v1 += bias[col + 1]; }
                if (relu) {
                    v0 = tf32r(fmaxf(v0, 0.f));
                    v1 = tf32r(fmaxf(v1, 0.f));
                }
                if (rrow) { v0 += rrow[col]; v1 += rrow[col + 1]; }
                float2 o; o.x = v0; o.y = v1;
                *(float2*)(crow + col) = o;
            }
        }
    }
}

// ---------------- attention: S = scale * Q @ K^T (reads fused qkv) ----------
__global__ __launch_bounds__(256) void attn_scores(
    const float* __restrict__ qkv, float* __restrict__ S)
{
    int jt = blockIdx.x, it = blockIdx.y, bh = blockIdx.z;
    if (jt > it) return;
    int b = bh >> 4, h = bh & 15;
    const float* Qb = qkv + ((size_t)b * TT + (size_t)it * 64) * C3 + h * 64;
    const float* Kb = qkv + ((size_t)b * TT + (size_t)jt * 64) * C3 + CC + h * 64;
    __shared__ float Qs[64][65];
    __shared__ float Ks[64][65];
    int tid = threadIdx.x;
#pragma unroll
    for (int p = 0; p < 4; p++) {
        int id4 = p * 256 + tid;
        int r = id4 >> 4;
        int c4 = (id4 & 15) << 2;
        float4 qv = *(const float4*)(Qb + (size_t)r * C3 + c4);
        Qs[r][c4] = qv.x; Qs[r][c4+1] = qv.y; Qs[r][c4+2] = qv.z; Qs[r][c4+3] = qv.w;
        float4 kv = *(const float4*)(Kb + (size_t)r * C3 + c4);
        Ks[r][c4] = kv.x; Ks[r][c4+1] = kv.y; Ks[r][c4+2] = kv.z; Ks[r][c4+3] = kv.w;
    }
    __syncthreads();
    int ty = tid >> 4, tx = tid & 15;
    float acc[4][4] = {};
#pragma unroll 4
    for (int d = 0; d < 64; d++) {
        float a[4], bb[4];
#pragma unroll
        for (int i = 0; i < 4; i++) a[i]  = Qs[(ty << 2) + i][d];
#pragma unroll
        for (int j = 0; j < 4; j++) bb[j] = Ks[(tx << 2) + j][d];
#pragma unroll
        for (int i = 0; i < 4; i++)
#pragma unroll
            for (int j = 0; j < 4; j++)
                acc[i][j] = fmaf(a[i], bb[j], acc[i][j]);
    }
    float* Sp = S + (size_t)bh * TT * TT;
#pragma unroll
    for (int i = 0; i < 4; i++) {
        int row = it * 64 + (ty << 2) + i;
#pragma unroll
        for (int j = 0; j < 4; j++)
            Sp[(size_t)row * TT + jt * 64 + (tx << 2) + j] = acc[i][j] * 0.125f;
    }
}

// ---------------- causal softmax over rows of S ------------------------------
__global__ __launch_bounds__(256) void attn_softmax(float* __restrict__ S)
{
    __shared__ float buf[256];
    int i = blockIdx.x, bh = blockIdx.y;
    float* row = S + (size_t)bh * TT * TT + (size_t)i * TT;
    int len = i + 1;
    float m = -3.4e38f;
    for (int j = threadIdx.x; j < len; j += 256) m = fmaxf(m, row[j]);
    m = block_reduce_max(m, buf);
    float s = 0.f;
    for (int j = threadIdx.x; j < len; j += 256) {
        float e = __expf(row[j] - m);
        row[j] = e; s += e;
    }
    s = block_reduce_sum(s, buf);
    float inv = 1.f / s;
    for (int j = threadIdx.x; j < len; j += 256) row[j] *= inv;
    int lim = ((i >> 6) + 1) << 6;
    for (int j = len + threadIdx.x; j < lim; j += 256) row[j] = 0.f;
}

// ---------------- O = P @ V (att output tf32-rounded: GEMM A input) ----------
__global__ __launch_bounds__(256) void attn_pv(
    const float* __restrict__ S, const float* __restrict__ qkv,
    float* __restrict__ o)
{
    int it = blockIdx.x, bh = blockIdx.y;
    int b = bh >> 4, h = bh & 15;
    const float* P  = S + (size_t)bh * TT * TT + (size_t)it * 64 * TT;
    const float* Vb = qkv + (size_t)b * TT * C3 + 2 * CC + h * 64;
    float* Ob = o + ((size_t)b * TT + (size_t)it * 64) * CC + h * 64;
    __shared__ float Ps[64][17];
    __shared__ float Vs[16][64];
    int tid = threadIdx.x, ty = tid >> 4, tx = tid & 15;
    float acc[4][4] = {};
    int kend = (it + 1) * 64;
    int pr = tid >> 2,  pc4 = (tid & 3) << 2;
    int vr = tid >> 4,  vc4 = (tid & 15) << 2;
    for (int k0 = 0; k0 < kend; k0 += 16) {
        float4 pv = *(const float4*)(P + (size_t)pr * TT + k0 + pc4);
        Ps[pr][pc4] = pv.x; Ps[pr][pc4+1] = pv.y; Ps[pr][pc4+2] = pv.z; Ps[pr][pc4+3] = pv.w;
        *(float4*)&Vs[vr][vc4] = *(const float4*)(Vb + (size_t)(k0 + vr) * C3 + vc4);
        __syncthreads();
#pragma unroll
        for (int kk = 0; kk < 16; kk++) {
            float a[4], bb[4];
#pragma unroll
            for (int i = 0; i < 4; i++) a[i]  = Ps[(ty << 2) + i][kk];
#pragma unroll
            for (int j = 0; j < 4; j++) bb[j] = Vs[kk][(tx << 2) + j];
#pragma unroll
            for (int i = 0; i < 4; i++)
#pragma unroll
                for (int j = 0; j < 4; j++)
                    acc[i][j] = fmaf(a[i], bb[j], acc[i][j]);
        }
        __syncthreads();
    }
#pragma unroll
    for (int i = 0; i < 4; i++)
#pragma unroll
        for (int j = 0; j < 4; j++)
            Ob[(size_t)((ty << 2) + i) * CC + (tx << 2) + j] = tf32r(acc[i][j]);
}

// ---------------- loss -------------------------------------------------------
__global__ __launch_bounds__(256) void row_loss_kernel(
    const float* __restrict__ logits, const int* __restrict__ targets,
    float* __restrict__ rl)
{
    __shared__ float buf[256];
    int row = blockIdx.x;
    const float* lr = logits + (size_t)row * VV;
    float m = -3.4e38f;
    for (int j = threadIdx.x; j < VV; j += 256) m = fmaxf(m, lr[j]);
    m = block_reduce_max(m, buf);
    float s = 0.f;
    for (int j = threadIdx.x; j < VV; j += 256) s += __expf(lr[j] - m);
    s = block_reduce_sum(s, buf);
    if (threadIdx.x == 0) {
        int t = targets[row];
        rl[row] = -(lr[t] - m - logf(s));
    }
}

__global__ __launch_bounds__(256) void loss_reduce_kernel(
    const float* __restrict__ rl, float* __restrict__ out)
{
    __shared__ float buf[256];
    float s = 0.f;
    for (int i = threadIdx.x; i < NN; i += 256) s += rl[i];
    s = block_reduce_sum(s, buf);
    if (threadIdx.x == 0) out[0] = s * (1.f / NN);
}

// ---------------- host orchestration ----------------------------------------
static inline void run_gemm(const float* A, const float* Wt, const float* bias,
                            const float* res, float* C, int M, int N, int K, int relu)
{
    int grid = (M / 128) * (N / 128);
    mma_gemm_kernel<<<grid, 256, GEMM_SMEM>>>(A, Wt, bias, res, C, M, N, K, relu);
}

extern "C" void kernel_launch(void* const* d_in, const int* in_sizes, int n_in,
                              void* d_out, int out_size)
{
    const int*   idx     = (const int*)  d_in[0];
    const int*   targets = (const int*)  d_in[1];
    const float* tok     = (const float*)d_in[2];
    const float* pos     = (const float*)d_in[3];
    const float* ln1_g   = (const float*)d_in[4];
    const float* ln1_b   = (const float*)d_in[5];
    const float* Wq      = (const float*)d_in[6];
    const float* Wk      = (const float*)d_in[7];
    const float* Wv      = (const float*)d_in[8];
    const float* Wo      = (const float*)d_in[9];
    const float* bo      = (const float*)d_in[10];
    const float* ln2_g   = (const float*)d_in[11];
    const float* ln2_b   = (const float*)d_in[12];
    const float* W1      = (const float*)d_in[13];
    const float* b1      = (const float*)d_in[14];
    const float* W2      = (const float*)d_in[15];
    const float* b2      = (const float*)d_in[16];
    const float* lnf_g   = (const float*)d_in[17];
    const float* lnf_b   = (const float*)d_in[18];
    const float* Wlm     = (const float*)d_in[19];
    const float* blm     = (const float*)d_in[20];
    (void)in_sizes; (void)n_in;

    cudaFuncSetAttribute(mma_gemm_kernel,
                         cudaFuncAttributeMaxDynamicSharedMemorySize, GEMM_SMEM);

    void* p;
    cudaGetSymbolAddress(&p, g_x);      float* x    = (float*)p;
    cudaGetSymbolAddress(&p, g_h);      float* h    = (float*)p;
    cudaGetSymbolAddress(&p, g_qkv);    float* qkv  = (float*)p;
    cudaGetSymbolAddress(&p, g_att);    float* att  = (float*)p;
    cudaGetSymbolAddress(&p, g_ffh);    float* ffh  = (float*)p;
    cudaGetSymbolAddress(&p, g_S);      float* S    = (float*)p;
    cudaGetSymbolAddress(&p, g_rowloss);float* rl   = (float*)p;
    cudaGetSymbolAddress(&p, g_logits_fb); float* logits_fb = (float*)p;
    cudaGetSymbolAddress(&p, g_WqkvT);  float* WqkvT = (float*)p;
    cudaGetSymbolAddress(&p, g_WoT);    float* WoT  = (float*)p;
    cudaGetSymbolAddress(&p, g_W1T);    float* W1T  = (float*)p;
    cudaGetSymbolAddress(&p, g_W2T);    float* W2T  = (float*)p;
    cudaGetSymbolAddress(&p, g_WlmT);   float* WlmT = (float*)p;

    const size_t NV = (size_t)NN * VV;
    float* out = (float*)d_out;
    bool big = ((size_t)out_size >= NV);
    float* logits   = big ? out : logits_fb;
    float* loss_dst = ((size_t)out_size > NV) ? out + NV
                    : (big ? rl + NN : out);

    // transpose all weights to [N,K] (tf32-rounded); QKV packed as [3C,K]
    transpose_kernel<<<dim3(CC/32, CC/32, LL), 256>>>(Wq, WqkvT + 0 * (size_t)CC * CC,
        CC, CC, (size_t)CC * CC, (size_t)C3 * CC);
    transpose_kernel<<<dim3(CC/32, CC/32, LL), 256>>>(Wk, WqkvT + 1 * (size_t)CC * CC,
        CC, CC, (size_t)CC * CC, (size_t)C3 * CC);
    transpose_kernel<<<dim3(CC/32, CC/32, LL), 256>>>(Wv, WqkvT + 2 * (size_t)CC * CC,
        CC, CC, (size_t)CC * CC, (size_t)C3 * CC);
    transpose_kernel<<<dim3(CC/32, CC/32, LL), 256>>>(Wo, WoT, CC, CC,
        (size_t)CC * CC, (size_t)CC * CC);
    transpose_kernel<<<dim3(FF/32, CC/32, LL), 256>>>(W1, W1T, CC, FF,
        (size_t)CC * FF, (size_t)CC * FF);
    transpose_kernel<<<dim3(CC/32, FF/32, LL), 256>>>(W2, W2T, FF, CC,
        (size_t)FF * CC, (size_t)FF * CC);
    transpose_kernel<<<dim3(VV/32, CC/32, 1),  256>>>(Wlm, WlmT, CC, VV, 0, 0);

    // embedding
    embed_kernel<<<(NN * CC) / 256, 256>>>(idx, tok, pos, x);

    for (int l = 0; l < LL; l++) {
        const size_t oC  = (size_t)l * CC;
        const size_t oCC = (size_t)l * CC * CC;
        const size_t oCF = (size_t)l * CC * FF;
        const size_t oF  = (size_t)l * FF;
        const size_t oQ  = (size_t)l * C3 * CC;

        ln_kernel<<<NN, 256>>>(x, ln1_g + oC, ln1_b + oC, h);
        run_gemm(h, WqkvT + oQ, nullptr, nullptr, qkv, NN, C3, CC, 0);

        attn_scores<<<dim3(TT / 64, TT / 64, BB * HH), 256>>>(qkv, S);
        attn_softmax<<<dim3(TT, BB * HH), 256>>>(S);
        attn_pv<<<dim3(TT / 64, BB * HH), 256>>>(S, qkv, att);

        run_gemm(att, WoT + oCC, bo + oC, x, x, NN, CC, CC, 0);

        ln_kernel<<<NN, 256>>>(x, ln2_g + oC, ln2_b + oC, h);
        run_gemm(h, W1T + oCF, b1 + oF, nullptr, ffh, NN, FF, CC, 1);
        run_gemm(ffh, W2T + oCF, b2 + oC, x, x, NN, CC, FF, 0);
    }

    ln_kernel<<<NN, 256>>>(x, lnf_g, lnf_b, h);
    run_gemm(h, WlmT, blm, nullptr, logits, NN, VV, CC, 0);

    row_loss_kernel<<<NN, 256>>>(logits, targets, rl);
    loss_reduce_kernel<<<1, 256>>>(rl, loss_dst);
}

// round 6
// speedup vs baseline: 1.7752x; 1.4111x over previous
#include <cuda_runtime.h>
#include <cuda_fp16.h>
#include <cstdint>

// Problem constants
#define BB 4
#define TT 1024
#define CC 1024
#define HH 16
#define HS 64
#define LL 12
#define VV 50304
#define NN (BB*TT)          // 4096 tokens
#define FF (4*CC)           // 4096
#define C3 (3*CC)           // 3072

// ---------------- scratch (device globals; no allocation allowed) -----------
__device__ float  g_x[NN*CC];
__device__ __half g_h[NN*CC];
__device__ float  g_qkv[(size_t)NN*C3];
__device__ __half g_att[NN*CC];
__device__ __half g_ffh[(size_t)NN*FF];
__device__ float  g_S[(size_t)BB*HH*TT*TT];      // 268 MB attention scores
__device__ float  g_rowloss[NN + 4];
__device__ float  g_logits_fb[(size_t)NN*VV];    // fallback if d_out too small
// transposed weights [N,K] (fp16)
__device__ __half g_WqkvT[(size_t)LL*C3*CC];     // rows: [Wq; Wk; Wv]
__device__ __half g_WoT[(size_t)LL*CC*CC];
__device__ __half g_W1T[(size_t)LL*CC*FF];
__device__ __half g_W2T[(size_t)LL*FF*CC];
__device__ __half g_WlmT[(size_t)CC*VV];

// ---------------- helpers ----------------------------------------------------
__device__ __forceinline__ uint32_t smem_u32(const void* p) {
    uint32_t a;
    asm("{ .reg .u64 t; cvta.to.shared.u64 t, %1; cvt.u32.u64 %0, t; }" : "=r"(a) : "l"(p));
    return a;
}
__device__ __forceinline__ uint32_t swz(uint32_t b) { return b ^ ((b >> 3) & 0x70); }

__device__ __forceinline__ void cp16(void* s, const void* g) {
    uint32_t sa = smem_u32(s);
    asm volatile("cp.async.cg.shared.global [%0], [%1], 16;" :: "r"(sa), "l"(g));
}
#define CP_COMMIT() asm volatile("cp.async.commit_group;" ::: "memory")
#define CP_WAIT(n)  asm volatile("cp.async.wait_group %0;" :: "n"(n) : "memory")

__device__ __forceinline__ void mma_f16(float* d, const uint32_t* a, const uint32_t* b) {
    asm volatile(
        "mma.sync.aligned.m16n8k16.row.col.f32.f16.f16.f32 "
        "{%0,%1,%2,%3}, {%4,%5,%6,%7}, {%8,%9}, {%0,%1,%2,%3};"
        : "+f"(d[0]), "+f"(d[1]), "+f"(d[2]), "+f"(d[3])
        : "r"(a[0]), "r"(a[1]), "r"(a[2]), "r"(a[3]), "r"(b[0]), "r"(b[1]));
}

// ---------------- reductions ------------------------------------------------
__device__ __forceinline__ float block_reduce_sum(float v, float* buf) {
    int tid = threadIdx.x;
    buf[tid] = v; __syncthreads();
    for (int s = 128; s > 0; s >>= 1) {
        if (tid < s) buf[tid] += buf[tid + s];
        __syncthreads();
    }
    float r = buf[0]; __syncthreads();
    return r;
}
__device__ __forceinline__ float block_reduce_max(float v, float* buf) {
    int tid = threadIdx.x;
    buf[tid] = v; __syncthreads();
    for (int s = 128; s > 0; s >>= 1) {
        if (tid < s) buf[tid] = fmaxf(buf[tid], buf[tid + s]);
        __syncthreads();
    }
    float r = buf[0]; __syncthreads();
    return r;
}

// ---------------- transpose: dst[N,K] = half(src[K,N]) ----------------------
__global__ __launch_bounds__(256) void transpose_kernel(
    const float* __restrict__ src, __half* __restrict__ dst, int K, int N,
    size_t src_zstride, size_t dst_zstride)
{
    __shared__ float t[32][33];
    const float* s = src + (size_t)blockIdx.z * src_zstride;
    __half* d = dst + (size_t)blockIdx.z * dst_zstride;
    int n0 = blockIdx.x << 5, k0 = blockIdx.y << 5;
    int tx = threadIdx.x & 31, ty = threadIdx.x >> 5;
#pragma unroll
    for (int p = 0; p < 4; p++)
        t[ty + p * 8][tx] = s[(size_t)(k0 + ty + p * 8) * N + n0 + tx];
    __syncthreads();
#pragma unroll
    for (int p = 0; p < 4; p++)
        d[(size_t)(n0 + ty + p * 8) * K + k0 + tx] = __float2half(t[tx][ty + p * 8]);
}

// ---------------- embedding -------------------------------------------------
__global__ __launch_bounds__(256) void embed_kernel(
    const int* __restrict__ idx, const float* __restrict__ tok,
    const float* __restrict__ pos, float* __restrict__ x)
{
    size_t i = (size_t)blockIdx.x * 256 + threadIdx.x;
    int n = (int)(i >> 10);
    int c = (int)(i & 1023);
    int t = n & (TT - 1);
    x[i] = tok[(size_t)idx[n] * CC + c] + pos[(size_t)t * CC + c];
}

// ---------------- layernorm (fp16 output: used only as GEMM A) --------------
__global__ __launch_bounds__(256) void ln_kernel(
    const float* __restrict__ x, const float* __restrict__ g,
    const float* __restrict__ b, __half* __restrict__ out)
{
    __shared__ float buf[256];
    int row = blockIdx.x;
    const float* xr = x + (size_t)row * CC;
    float s = 0.f, ss = 0.f;
    for (int c = threadIdx.x; c < CC; c += 256) {
        float v = xr[c]; s += v; ss += v * v;
    }
    s  = block_reduce_sum(s, buf);
    ss = block_reduce_sum(ss, buf);
    float mu  = s * (1.f / CC);
    float inv = rsqrtf(ss * (1.f / CC) - mu * mu + 1e-5f);
    __half* orow = out + (size_t)row * CC;
    for (int c = threadIdx.x; c < CC; c += 256)
        orow[c] = __float2half((xr[c] - mu) * inv * g[c] + b[c]);
}

// ---------------- mma.sync fp16 GEMM: C = A[M,K] @ Bt[N,K]^T -----------------
// BM=128, BN=128, BK=64, 256 threads (8 warps, 2x4), 3-stage cp.async pipeline.
// Full register budget: register-limited to 1 CTA/SM — do NOT cap regs.
// Output: fp32 C (optionally + residual/bias) or fp16 Ch (with relu for MLP).
#define GEMM_SMEM (3*32768)
#define GW 16
__global__ __launch_bounds__(256) void mma_gemm_kernel(
    const __half* __restrict__ A, const __half* __restrict__ Bt,
    const float* __restrict__ bias, const float* __restrict__ res,
    float* __restrict__ C, __half* __restrict__ Ch,
    int M, int N, int K, int relu)
{
    extern __shared__ char smem[];
    int tid = threadIdx.x;
    int wid = tid >> 5, lane = tid & 31;
    int g = lane >> 2, q = lane & 3;
    int wm0 = (wid >> 2) << 6;      // 0 or 64
    int wn0 = (wid & 3) << 5;       // 0,32,64,96

    int Mb = M >> 7, Nb = N >> 7;
    int bid = blockIdx.x;
    int group = bid / (Mb * GW);
    int rem = bid - group * Mb * GW;
    int gw = Nb - group * GW; if (gw > GW) gw = GW;
    int n_blk = group * GW + rem % gw;
    int m_blk = rem / gw;
    int m0 = m_blk << 7, n0 = n_blk << 7;

    const __half* Abase = A + (size_t)m0 * K;
    const __half* Bbase = Bt + (size_t)n0 * K;
    int Kc = K >> 6;

    float acc[4][4][4] = {};

    // prefetch stages 0,1 (each stage: A 128x64 fp16 =16KB + B 16KB)
#pragma unroll
    for (int c = 0; c < 2; c++) {
        char* sa = smem + c * 32768;
        char* sbm = sa + 16384;
#pragma unroll
        for (int p = 0; p < 4; p++) {
            int id = p * 256 + tid;
            int row = id >> 3, ch = id & 7;
            uint32_t off = swz((row << 7) + (ch << 4));
            cp16(sa + off, Abase + (size_t)row * K + (c << 6) + (ch << 3));
            cp16(sbm + off, Bbase + (size_t)row * K + (c << 6) + (ch << 3));
        }
        CP_COMMIT();
    }

    for (int c = 0; c < Kc; c++) {
        if (c + 2 < Kc) { CP_WAIT(1); } else { CP_WAIT(0); }
        __syncthreads();
        if (c + 2 < Kc) {
            int cs = c + 2;
            char* sa = smem + (cs % 3) * 32768;
            char* sbm = sa + 16384;
#pragma unroll
            for (int p = 0; p < 4; p++) {
                int id = p * 256 + tid;
                int row = id >> 3, ch = id & 7;
                uint32_t off = swz((row << 7) + (ch << 4));
                cp16(sa + off, Abase + (size_t)row * K + (cs << 6) + (ch << 3));
                cp16(sbm + off, Bbase + (size_t)row * K + (cs << 6) + (ch << 3));
            }
            CP_COMMIT();
        }
        const char* As = smem + (c % 3) * 32768;
        const char* Bs = As + 16384;
#pragma unroll
        for (int ks = 0; ks < 4; ks++) {
            int kb = ks << 5;   // byte offset of k-step within 128-byte row
            uint32_t af[4][4];
#pragma unroll
            for (int mi = 0; mi < 4; mi++) {
                int r = wm0 + (mi << 4) + g;
                af[mi][0] = *(const uint32_t*)(As + swz((r << 7) + kb + (q << 2)));
                af[mi][1] = *(const uint32_t*)(As + swz(((r + 8) << 7) + kb + (q << 2)));
                af[mi][2] = *(const uint32_t*)(As + swz((r << 7) + kb + 16 + (q << 2)));
                af[mi][3] = *(const uint32_t*)(As + swz(((r + 8) << 7) + kb + 16 + (q << 2)));
            }
            uint32_t bf[4][2];
#pragma unroll
            for (int ni = 0; ni < 4; ni++) {
                int n = wn0 + (ni << 3) + g;
                bf[ni][0] = *(const uint32_t*)(Bs + swz((n << 7) + kb + (q << 2)));
                bf[ni][1] = *(const uint32_t*)(Bs + swz((n << 7) + kb + 16 + (q << 2)));
            }
#pragma unroll
            for (int mi = 0; mi < 4; mi++)
#pragma unroll
                for (int ni = 0; ni < 4; ni++)
                    mma_f16(acc[mi][ni], af[mi], bf[ni]);
        }
    }

    // epilogue
#pragma unroll
    for (int mi = 0; mi < 4; mi++) {
#pragma unroll
        for (int half = 0; half < 2; half++) {
            int row = m0 + wm0 + (mi << 4) + g + half * 8;
            const float* rrow = res ? res + (size_t)row * N : nullptr;
#pragma unroll
            for (int ni = 0; ni < 4; ni++) {
                int col = n0 + wn0 + (ni << 3) + (q << 1);
                float v0 = acc[mi][ni][half * 2 + 0];
                float v1 = acc[mi][ni][half * 2 + 1];
                if (bias) { v0 += bias[col]; v1 += bias[col + 1]; }
                if (relu) { v0 = fmaxf(v0, 0.f); v1 = fmaxf(v1, 0.f); }
                if (rrow) { v0 += rrow[col]; v1 += rrow[col + 1]; }
                if (Ch) {
                    __half2 o; o.x = __float2half(v0); o.y = __float2half(v1);
                    *(__half2*)(Ch + (size_t)row * N + col) = o;
                } else {
                    float2 o; o.x = v0; o.y = v1;
                    *(float2*)(C + (size_t)row * N + col) = o;
                }
            }
        }
    }
}

// ---------------- attention: S = scale * Q @ K^T (reads fused qkv) ----------
__global__ __launch_bounds__(256) void attn_scores(
    const float* __restrict__ qkv, float* __restrict__ S)
{
    int jt = blockIdx.x, it = blockIdx.y, bh = blockIdx.z;
    if (jt > it) return;
    int b = bh >> 4, h = bh & 15;
    const float* Qb = qkv + ((size_t)b * TT + (size_t)it * 64) * C3 + h * 64;
    const float* Kb = qkv + ((size_t)b * TT + (size_t)jt * 64) * C3 + CC + h * 64;
    __shared__ float Qs[64][65];
    __shared__ float Ks[64][65];
    int tid = threadIdx.x;
#pragma unroll
    for (int p = 0; p < 4; p++) {
        int id4 = p * 256 + tid;
        int r = id4 >> 4;
        int c4 = (id4 & 15) << 2;
        float4 qv = *(const float4*)(Qb + (size_t)r * C3 + c4);
        Qs[r][c4] = qv.x; Qs[r][c4+1] = qv.y; Qs[r][c4+2] = qv.z; Qs[r][c4+3] = qv.w;
        float4 kv = *(const float4*)(Kb + (size_t)r * C3 + c4);
        Ks[r][c4] = kv.x; Ks[r][c4+1] = kv.y; Ks[r][c4+2] = kv.z; Ks[r][c4+3] = kv.w;
    }
    __syncthreads();
    int ty = tid >> 4, tx = tid & 15;
    float acc[4][4] = {};
#pragma unroll 4
    for (int d = 0; d < 64; d++) {
        float a[4], bb[4];
#pragma unroll
        for (int i = 0; i < 4; i++) a[i]  = Qs[(ty << 2) + i][d];
#pragma unroll
        for (int j = 0; j < 4; j++) bb[j] = Ks[(tx << 2) + j][d];
#pragma unroll
        for (int i = 0; i < 4; i++)
#pragma unroll
            for (int j = 0; j < 4; j++)
                acc[i][j] = fmaf(a[i], bb[j], acc[i][j]);
    }
    float* Sp = S + (size_t)bh * TT * TT;
#pragma unroll
    for (int i = 0; i < 4; i++) {
        int row = it * 64 + (ty << 2) + i;
#pragma unroll
        for (int j = 0; j < 4; j++)
            Sp[(size_t)row * TT + jt * 64 + (tx << 2) + j] = acc[i][j] * 0.125f;
    }
}

// ---------------- causal softmax over rows of S ------------------------------
__global__ __launch_bounds__(256) void attn_softmax(float* __restrict__ S)
{
    __shared__ float buf[256];
    int i = blockIdx.x, bh = blockIdx.y;
    float* row = S + (size_t)bh * TT * TT + (size_t)i * TT;
    int len = i + 1;
    float m = -3.4e38f;
    for (int j = threadIdx.x; j < len; j += 256) m = fmaxf(m, row[j]);
    m = block_reduce_max(m, buf);
    float s = 0.f;
    for (int j = threadIdx.x; j < len; j += 256) {
        float e = __expf(row[j] - m);
        row[j] = e; s += e;
    }
    s = block_reduce_sum(s, buf);
    float inv = 1.f / s;
    for (int j = threadIdx.x; j < len; j += 256) row[j] *= inv;
    int lim = ((i >> 6) + 1) << 6;
    for (int j = len + threadIdx.x; j < lim; j += 256) row[j] = 0.f;
}

// ---------------- O = P @ V (fp16 output: GEMM A input) ----------------------
__global__ __launch_bounds__(256) void attn_pv(
    const float* __restrict__ S, const float* __restrict__ qkv,
    __half* __restrict__ o)
{
    int it = blockIdx.x, bh = blockIdx.y;
    int b = bh >> 4, h = bh & 15;
    const float* P  = S + (size_t)bh * TT * TT + (size_t)it * 64 * TT;
    const float* Vb = qkv + (size_t)b * TT * C3 + 2 * CC + h * 64;
    __half* Ob = o + ((size_t)b * TT + (size_t)it * 64) * CC + h * 64;
    __shared__ float Ps[64][17];
    __shared__ float Vs[16][64];
    int tid = threadIdx.x, ty = tid >> 4, tx = tid & 15;
    float acc[4][4] = {};
    int kend = (it + 1) * 64;
    int pr = tid >> 2,  pc4 = (tid & 3) << 2;
    int vr = tid >> 4,  vc4 = (tid & 15) << 2;
    for (int k0 = 0; k0 < kend; k0 += 16) {
        float4 pv = *(const float4*)(P + (size_t)pr * TT + k0 + pc4);
        Ps[pr][pc4] = pv.x; Ps[pr][pc4+1] = pv.y; Ps[pr][pc4+2] = pv.z; Ps[pr][pc4+3] = pv.w;
        *(float4*)&Vs[vr][vc4] = *(const float4*)(Vb + (size_t)(k0 + vr) * C3 + vc4);
        __syncthreads();
#pragma unroll
        for (int kk = 0; kk < 16; kk++) {
            float a[4], bb[4];
#pragma unroll
            for (int i = 0; i < 4; i++) a[i]  = Ps[(ty << 2) + i][kk];
#pragma unroll
            for (int j = 0; j < 4; j++) bb[j] = Vs[kk][(tx << 2) + j];
#pragma unroll
            for (int i = 0; i < 4; i++)
#pragma unroll
                for (int j = 0; j < 4; j++)
                    acc[i][j] = fmaf(a[i], bb[j], acc[i][j]);
        }
        __syncthreads();
    }
#pragma unroll
    for (int i = 0; i < 4; i++)
#pragma unroll
        for (int j = 0; j < 4; j++)
            Ob[(size_t)((ty << 2) + i) * CC + (tx << 2) + j] = __float2half(acc[i][j]);
}

// ---------------- loss -------------------------------------------------------
__global__ __launch_bounds__(256) void row_loss_kernel(
    const float* __restrict__ logits, const int* __restrict__ targets,
    float* __restrict__ rl)
{
    __shared__ float buf[256];
    int row = blockIdx.x;
    const float* lr = logits + (size_t)row * VV;
    float m = -3.4e38f;
    for (int j = threadIdx.x; j < VV; j += 256) m = fmaxf(m, lr[j]);
    m = block_reduce_max(m, buf);
    float s = 0.f;
    for (int j = threadIdx.x; j < VV; j += 256) s += __expf(lr[j] - m);
    s = block_reduce_sum(s, buf);
    if (threadIdx.x == 0) {
        int t = targets[row];
        rl[row] = -(lr[t] - m - logf(s));
    }
}

__global__ __launch_bounds__(256) void loss_reduce_kernel(
    const float* __restrict__ rl, float* __restrict__ out)
{
    __shared__ float buf[256];
    float s = 0.f;
    for (int i = threadIdx.x; i < NN; i += 256) s += rl[i];
    s = block_reduce_sum(s, buf);
    if (threadIdx.x == 0) out[0] = s * (1.f / NN);
}

// ---------------- host orchestration ----------------------------------------
static inline void run_gemm(const __half* A, const __half* Wt, const float* bias,
                            const float* res, float* C, __half* Ch,
                            int M, int N, int K, int relu)
{
    int grid = (M / 128) * (N / 128);
    mma_gemm_kernel<<<grid, 256, GEMM_SMEM>>>(A, Wt, bias, res, C, Ch, M, N, K, relu);
}

extern "C" void kernel_launch(void* const* d_in, const int* in_sizes, int n_in,
                              void* d_out, int out_size)
{
    const int*   idx     = (const int*)  d_in[0];
    const int*   targets = (const int*)  d_in[1];
    const float* tok     = (const float*)d_in[2];
    const float* pos     = (const float*)d_in[3];
    const float* ln1_g   = (const float*)d_in[4];
    const float* ln1_b   = (const float*)d_in[5];
    const float* Wq      = (const float*)d_in[6];
    const float* Wk      = (const float*)d_in[7];
    const float* Wv      = (const float*)d_in[8];
    const float* Wo      = (const float*)d_in[9];
    const float* bo      = (const float*)d_in[10];
    const float* ln2_g   = (const float*)d_in[11];
    const float* ln2_b   = (const float*)d_in[12];
    const float* W1      = (const float*)d_in[13];
    const float* b1      = (const float*)d_in[14];
    const float* W2      = (const float*)d_in[15];
    const float* b2      = (const float*)d_in[16];
    const float* lnf_g   = (const float*)d_in[17];
    const float* lnf_b   = (const float*)d_in[18];
    const float* Wlm     = (const float*)d_in[19];
    const float* blm     = (const float*)d_in[20];
    (void)in_sizes; (void)n_in;

    cudaFuncSetAttribute(mma_gemm_kernel,
                         cudaFuncAttributeMaxDynamicSharedMemorySize, GEMM_SMEM);

    void* p;
    cudaGetSymbolAddress(&p, g_x);      float*  x    = (float*)p;
    cudaGetSymbolAddress(&p, g_h);      __half* h    = (__half*)p;
    cudaGetSymbolAddress(&p, g_qkv);    float*  qkv  = (float*)p;
    cudaGetSymbolAddress(&p, g_att);    __half* att  = (__half*)p;
    cudaGetSymbolAddress(&p, g_ffh);    __half* ffh  = (__half*)p;
    cudaGetSymbolAddress(&p, g_S);      float*  S    = (float*)p;
    cudaGetSymbolAddress(&p, g_rowloss);float*  rl   = (float*)p;
    cudaGetSymbolAddress(&p, g_logits_fb); float* logits_fb = (float*)p;
    cudaGetSymbolAddress(&p, g_WqkvT);  __half* WqkvT = (__half*)p;
    cudaGetSymbolAddress(&p, g_WoT);    __half* WoT  = (__half*)p;
    cudaGetSymbolAddress(&p, g_W1T);    __half* W1T  = (__half*)p;
    cudaGetSymbolAddress(&p, g_W2T);    __half* W2T  = (__half*)p;
    cudaGetSymbolAddress(&p, g_WlmT);   __half* WlmT = (__half*)p;

    const size_t NV = (size_t)NN * VV;
    float* out = (float*)d_out;
    bool big = ((size_t)out_size >= NV);
    float* logits   = big ? out : logits_fb;
    float* loss_dst = ((size_t)out_size > NV) ? out + NV
                    : (big ? rl + NN : out);

    // transpose all weights to fp16 [N,K]; QKV packed as [3C,K]
    transpose_kernel<<<dim3(CC/32, CC/32, LL), 256>>>(Wq, WqkvT + 0 * (size_t)CC * CC,
        CC, CC, (size_t)CC * CC, (size_t)C3 * CC);
    transpose_kernel<<<dim3(CC/32, CC/32, LL), 256>>>(Wk, WqkvT + 1 * (size_t)CC * CC,
        CC, CC, (size_t)CC * CC, (size_t)C3 * CC);
    transpose_kernel<<<dim3(CC/32, CC/32, LL), 256>>>(Wv, WqkvT + 2 * (size_t)CC * CC,
        CC, CC, (size_t)CC * CC, (size_t)C3 * CC);
    transpose_kernel<<<dim3(CC/32, CC/32, LL), 256>>>(Wo, WoT, CC, CC,
        (size_t)CC * CC, (size_t)CC * CC);
    transpose_kernel<<<dim3(FF/32, CC/32, LL), 256>>>(W1, W1T, CC, FF,
        (size_t)CC * FF, (size_t)CC * FF);
    transpose_kernel<<<dim3(CC/32, FF/32, LL), 256>>>(W2, W2T, FF, CC,
        (size_t)FF * CC, (size_t)FF * CC);
    transpose_kernel<<<dim3(VV/32, CC/32, 1),  256>>>(Wlm, WlmT, CC, VV, 0, 0);

    // embedding
    embed_kernel<<<(NN * CC) / 256, 256>>>(idx, tok, pos, x);

    for (int l = 0; l < LL; l++) {
        const size_t oC  = (size_t)l * CC;
        const size_t oCC = (size_t)l * CC * CC;
        const size_t oCF = (size_t)l * CC * FF;
        const size_t oF  = (size_t)l * FF;
        const size_t oQ  = (size_t)l * C3 * CC;

        ln_kernel<<<NN, 256>>>(x, ln1_g + oC, ln1_b + oC, h);
        run_gemm(h, WqkvT + oQ, nullptr, nullptr, qkv, nullptr, NN, C3, CC, 0);

        attn_scores<<<dim3(TT / 64, TT / 64, BB * HH), 256>>>(qkv, S);
        attn_softmax<<<dim3(TT, BB * HH), 256>>>(S);
        attn_pv<<<dim3(TT / 64, BB * HH), 256>>>(S, qkv, att);

        run_gemm(att, WoT + oCC, bo + oC, x, x, nullptr, NN, CC, CC, 0);

        ln_kernel<<<NN, 256>>>(x, ln2_g + oC, ln2_b + oC, h);
        run_gemm(h, W1T + oCF, b1 + oF, nullptr, nullptr, ffh, NN, FF, CC, 1);
        run_gemm(ffh, W2T + oCF, b2 + oC, x, x, nullptr, NN, CC, FF, 0);
    }

    ln_kernel<<<NN, 256>>>(x, lnf_g, lnf_b, h);
    run_gemm(h, WlmT, blm, nullptr, logits, nullptr, NN, VV, CC, 0);

    row_loss_kernel<<<NN, 256>>>(logits, targets, rl);
    loss_reduce_kernel<<<1, 256>>>(rl, loss_dst);
}

// round 7
// speedup vs baseline: 3.1019x; 1.7474x over previous
#include <cuda_runtime.h>
#include <cuda_fp16.h>
#include <cstdint>

// Problem constants
#define BB 4
#define TT 1024
#define CC 1024
#define HH 16
#define HS 64
#define LL 12
#define VV 50304
#define NN (BB*TT)          // 4096 tokens
#define FF (4*CC)           // 4096
#define C3 (3*CC)           // 3072

// ---------------- scratch (device globals; no allocation allowed) -----------
__device__ float  g_x[NN*CC];
__device__ __half g_h[NN*CC];
__device__ __half g_qkv[(size_t)NN*C3];
__device__ __half g_att[NN*CC];
__device__ __half g_ffh[(size_t)NN*FF];
__device__ float  g_rowloss[NN + 4];
__device__ float  g_logits_fb[(size_t)NN*VV];    // fallback if d_out too small
// transposed weights [N,K] (fp16)
__device__ __half g_WqkvT[(size_t)LL*C3*CC];     // rows: [Wq; Wk; Wv]
__device__ __half g_WoT[(size_t)LL*CC*CC];
__device__ __half g_W1T[(size_t)LL*CC*FF];
__device__ __half g_W2T[(size_t)LL*FF*CC];
__device__ __half g_WlmT[(size_t)CC*VV];

// ---------------- helpers ----------------------------------------------------
__device__ __forceinline__ uint32_t smem_u32(const void* p) {
    uint32_t a;
    asm("{ .reg .u64 t; cvta.to.shared.u64 t, %1; cvt.u32.u64 %0, t; }" : "=r"(a) : "l"(p));
    return a;
}
__device__ __forceinline__ uint32_t swz(uint32_t b) { return b ^ ((b >> 3) & 0x70); }

__device__ __forceinline__ void cp16(void* s, const void* g) {
    uint32_t sa = smem_u32(s);
    asm volatile("cp.async.cg.shared.global [%0], [%1], 16;" :: "r"(sa), "l"(g));
}
#define CP_COMMIT() asm volatile("cp.async.commit_group;" ::: "memory")
#define CP_WAIT(n)  asm volatile("cp.async.wait_group %0;" :: "n"(n) : "memory")

__device__ __forceinline__ void mma_f16(float* d, const uint32_t* a, const uint32_t* b) {
    asm volatile(
        "mma.sync.aligned.m16n8k16.row.col.f32.f16.f16.f32 "
        "{%0,%1,%2,%3}, {%4,%5,%6,%7}, {%8,%9}, {%0,%1,%2,%3};"
        : "+f"(d[0]), "+f"(d[1]), "+f"(d[2]), "+f"(d[3])
        : "r"(a[0]), "r"(a[1]), "r"(a[2]), "r"(a[3]), "r"(b[0]), "r"(b[1]));
}
__device__ __forceinline__ void ldsm_x4_t(uint32_t& r0, uint32_t& r1,
                                          uint32_t& r2, uint32_t& r3, uint32_t addr) {
    asm volatile("ldmatrix.sync.aligned.m8n8.x4.trans.shared.b16 {%0,%1,%2,%3}, [%4];"
        : "=r"(r0), "=r"(r1), "=r"(r2), "=r"(r3) : "r"(addr));
}
__device__ __forceinline__ uint32_t packh2(float a, float b) {
    __half2 h = __floats2half2_rn(a, b);
    return *(uint32_t*)&h;
}

// ---------------- reductions ------------------------------------------------
__device__ __forceinline__ float block_reduce_sum(float v, float* buf) {
    int tid = threadIdx.x;
    buf[tid] = v; __syncthreads();
    for (int s = 128; s > 0; s >>= 1) {
        if (tid < s) buf[tid] += buf[tid + s];
        __syncthreads();
    }
    float r = buf[0]; __syncthreads();
    return r;
}
__device__ __forceinline__ float block_reduce_max(float v, float* buf) {
    int tid = threadIdx.x;
    buf[tid] = v; __syncthreads();
    for (int s = 128; s > 0; s >>= 1) {
        if (tid < s) buf[tid] = fmaxf(buf[tid], buf[tid + s]);
        __syncthreads();
    }
    float r = buf[0]; __syncthreads();
    return r;
}

// ---------------- transpose: dst[N,K] = half(src[K,N]) ----------------------
__global__ __launch_bounds__(256) void transpose_kernel(
    const float* __restrict__ src, __half* __restrict__ dst, int K, int N,
    size_t src_zstride, size_t dst_zstride)
{
    __shared__ float t[32][33];
    const float* s = src + (size_t)blockIdx.z * src_zstride;
    __half* d = dst + (size_t)blockIdx.z * dst_zstride;
    int n0 = blockIdx.x << 5, k0 = blockIdx.y << 5;
    int tx = threadIdx.x & 31, ty = threadIdx.x >> 5;
#pragma unroll
    for (int p = 0; p < 4; p++)
        t[ty + p * 8][tx] = s[(size_t)(k0 + ty + p * 8) * N + n0 + tx];
    __syncthreads();
#pragma unroll
    for (int p = 0; p < 4; p++)
        d[(size_t)(n0 + ty + p * 8) * K + k0 + tx] = __float2half(t[tx][ty + p * 8]);
}

// ---------------- embedding -------------------------------------------------
__global__ __launch_bounds__(256) void embed_kernel(
    const int* __restrict__ idx, const float* __restrict__ tok,
    const float* __restrict__ pos, float* __restrict__ x)
{
    size_t i = (size_t)blockIdx.x * 256 + threadIdx.x;
    int n = (int)(i >> 10);
    int c = (int)(i & 1023);
    int t = n & (TT - 1);
    x[i] = tok[(size_t)idx[n] * CC + c] + pos[(size_t)t * CC + c];
}

// ---------------- layernorm (fp16 output: used only as GEMM A) --------------
__global__ __launch_bounds__(256) void ln_kernel(
    const float* __restrict__ x, const float* __restrict__ g,
    const float* __restrict__ b, __half* __restrict__ out)
{
    __shared__ float buf[256];
    int row = blockIdx.x;
    const float* xr = x + (size_t)row * CC;
    float s = 0.f, ss = 0.f;
    for (int c = threadIdx.x; c < CC; c += 256) {
        float v = xr[c]; s += v; ss += v * v;
    }
    s  = block_reduce_sum(s, buf);
    ss = block_reduce_sum(ss, buf);
    float mu  = s * (1.f / CC);
    float inv = rsqrtf(ss * (1.f / CC) - mu * mu + 1e-5f);
    __half* orow = out + (size_t)row * CC;
    for (int c = threadIdx.x; c < CC; c += 256)
        orow[c] = __float2half((xr[c] - mu) * inv * g[c] + b[c]);
}

// ---------------- mma.sync fp16 GEMM: C = A[M,K] @ Bt[N,K]^T -----------------
// BM=128, BN=128, BK=64, 256 threads (8 warps, 2x4), 3-stage cp.async pipeline.
// Full register budget: register-limited to 1 CTA/SM — do NOT cap regs.
#define GEMM_SMEM (3*32768)
#define GW 16
__global__ __launch_bounds__(256) void mma_gemm_kernel(
    const __half* __restrict__ A, const __half* __restrict__ Bt,
    const float* __restrict__ bias, const float* __restrict__ res,
    float* __restrict__ C, __half* __restrict__ Ch,
    int M, int N, int K, int relu)
{
    extern __shared__ char smem[];
    int tid = threadIdx.x;
    int wid = tid >> 5, lane = tid & 31;
    int g = lane >> 2, q = lane & 3;
    int wm0 = (wid >> 2) << 6;
    int wn0 = (wid & 3) << 5;

    int Mb = M >> 7, Nb = N >> 7;
    int bid = blockIdx.x;
    int group = bid / (Mb * GW);
    int rem = bid - group * Mb * GW;
    int gw = Nb - group * GW; if (gw > GW) gw = GW;
    int n_blk = group * GW + rem % gw;
    int m_blk = rem / gw;
    int m0 = m_blk << 7, n0 = n_blk << 7;

    const __half* Abase = A + (size_t)m0 * K;
    const __half* Bbase = Bt + (size_t)n0 * K;
    int Kc = K >> 6;

    float acc[4][4][4] = {};

#pragma unroll
    for (int c = 0; c < 2; c++) {
        char* sa = smem + c * 32768;
        char* sbm = sa + 16384;
#pragma unroll
        for (int p = 0; p < 4; p++) {
            int id = p * 256 + tid;
            int row = id >> 3, ch = id & 7;
            uint32_t off = swz((row << 7) + (ch << 4));
            cp16(sa + off, Abase + (size_t)row * K + (c << 6) + (ch << 3));
            cp16(sbm + off, Bbase + (size_t)row * K + (c << 6) + (ch << 3));
        }
        CP_COMMIT();
    }

    for (int c = 0; c < Kc; c++) {
        if (c + 2 < Kc) { CP_WAIT(1); } else { CP_WAIT(0); }
        __syncthreads();
        if (c + 2 < Kc) {
            int cs = c + 2;
            char* sa = smem + (cs % 3) * 32768;
            char* sbm = sa + 16384;
#pragma unroll
            for (int p = 0; p < 4; p++) {
                int id = p * 256 + tid;
                int row = id >> 3, ch = id & 7;
                uint32_t off = swz((row << 7) + (ch << 4));
                cp16(sa + off, Abase + (size_t)row * K + (cs << 6) + (ch << 3));
                cp16(sbm + off, Bbase + (size_t)row * K + (cs << 6) + (ch << 3));
            }
            CP_COMMIT();
        }
        const char* As = smem + (c % 3) * 32768;
        const char* Bs = As + 16384;
#pragma unroll
        for (int ks = 0; ks < 4; ks++) {
            int kb = ks << 5;
            uint32_t af[4][4];
#pragma unroll
            for (int mi = 0; mi < 4; mi++) {
                int r = wm0 + (mi << 4) + g;
                af[mi][0] = *(const uint32_t*)(As + swz((r << 7) + kb + (q << 2)));
                af[mi][1] = *(const uint32_t*)(As + swz(((r + 8) << 7) + kb + (q << 2)));
                af[mi][2] = *(const uint32_t*)(As + swz((r << 7) + kb + 16 + (q << 2)));
                af[mi][3] = *(const uint32_t*)(As + swz(((r + 8) << 7) + kb + 16 + (q << 2)));
            }
            uint32_t bf[4][2];
#pragma unroll
            for (int ni = 0; ni < 4; ni++) {
                int n = wn0 + (ni << 3) + g;
                bf[ni][0] = *(const uint32_t*)(Bs + swz((n << 7) + kb + (q << 2)));
                bf[ni][1] = *(const uint32_t*)(Bs + swz((n << 7) + kb + 16 + (q << 2)));
            }
#pragma unroll
            for (int mi = 0; mi < 4; mi++)
#pragma unroll
                for (int ni = 0; ni < 4; ni++)
                    mma_f16(acc[mi][ni], af[mi], bf[ni]);
        }
    }

#pragma unroll
    for (int mi = 0; mi < 4; mi++) {
#pragma unroll
        for (int half = 0; half < 2; half++) {
            int row = m0 + wm0 + (mi << 4) + g + half * 8;
            const float* rrow = res ? res + (size_t)row * N : nullptr;
#pragma unroll
            for (int ni = 0; ni < 4; ni++) {
                int col = n0 + wn0 + (ni << 3) + (q << 1);
                float v0 = acc[mi][ni][half * 2 + 0];
                float v1 = acc[mi][ni][half * 2 + 1];
                if (bias) { v0 += bias[col]; v1 += bias[col + 1]; }
                if (relu) { v0 = fmaxf(v0, 0.f); v1 = fmaxf(v1, 0.f); }
                if (rrow) { v0 += rrow[col]; v1 += rrow[col + 1]; }
                if (Ch) {
                    *(uint32_t*)(Ch + (size_t)row * N + col) = packh2(v0, v1);
                } else {
                    float2 o; o.x = v0; o.y = v1;
                    *(float2*)(C + (size_t)row * N + col) = o;
                }
            }
        }
    }
}

// ---------------- fused flash attention --------------------------------------
// CTA: 64 query rows x head 64, 128 threads (4 warps, m16 each).
// Iterates causal key tiles of 64 with online softmax; K/V double-buffered.
__global__ __launch_bounds__(128) void flash_attn(
    const __half* __restrict__ qkv, __half* __restrict__ o)
{
    __shared__ __align__(16) __half Qs[64 * 64];
    __shared__ __align__(16) __half Ks[2][64 * 64];
    __shared__ __align__(16) __half Vs[2][64 * 64];

    int it = (int)gridDim.x - 1 - (int)blockIdx.x;   // longest tiles first
    int bh = blockIdx.y;
    int b = bh >> 4, h = bh & 15;
    int tid = threadIdx.x;
    int wid = tid >> 5, lane = tid & 31;
    int g = lane >> 2, q = lane & 3;
    int wr = wid << 4;                               // warp's query-row base

    const __half* Qg = qkv + ((size_t)b * TT + (size_t)it * 64) * C3 + h * 64;

    // load Q tile
#pragma unroll
    for (int p = 0; p < 4; p++) {
        int id = p * 128 + tid;
        int row = id >> 3, ch = id & 7;
        cp16((char*)Qs + swz((row << 7) + (ch << 4)), Qg + (size_t)row * C3 + (ch << 3));
    }
    CP_COMMIT();

    // load K/V tile 0
    {
        const __half* Kg = qkv + (size_t)b * TT * C3 + CC + h * 64;
        const __half* Vg = qkv + (size_t)b * TT * C3 + 2 * CC + h * 64;
#pragma unroll
        for (int p = 0; p < 4; p++) {
            int id = p * 128 + tid;
            int row = id >> 3, ch = id & 7;
            uint32_t off = swz((row << 7) + (ch << 4));
            cp16((char*)Ks[0] + off, Kg + (size_t)row * C3 + (ch << 3));
            cp16((char*)Vs[0] + off, Vg + (size_t)row * C3 + (ch << 3));
        }
        CP_COMMIT();
    }

    float m0 = -1e30f, m1 = -1e30f;
    float l0 = 0.f, l1 = 0.f;
    float oacc[8][4] = {};

    for (int jt = 0; jt <= it; jt++) {
        int buf = jt & 1;
        if (jt < it) {
            int nb = (jt + 1) & 1;
            const __half* Kg = qkv + ((size_t)b * TT + (size_t)(jt + 1) * 64) * C3 + CC + h * 64;
            const __half* Vg = qkv + ((size_t)b * TT + (size_t)(jt + 1) * 64) * C3 + 2 * CC + h * 64;
#pragma unroll
            for (int p = 0; p < 4; p++) {
                int id = p * 128 + tid;
                int row = id >> 3, ch = id & 7;
                uint32_t off = swz((row << 7) + (ch << 4));
                cp16((char*)Ks[nb] + off, Kg + (size_t)row * C3 + (ch << 3));
                cp16((char*)Vs[nb] + off, Vg + (size_t)row * C3 + (ch << 3));
            }
            CP_COMMIT();
            CP_WAIT(1);
        } else {
            CP_WAIT(0);
        }
        __syncthreads();

        // S = Q @ K^T
        float sacc[8][4] = {};
        const char* Qb = (const char*)Qs;
        const char* Kb = (const char*)Ks[buf];
#pragma unroll
        for (int ks = 0; ks < 4; ks++) {
            int kb = ks << 5;
            uint32_t af[4];
            af[0] = *(const uint32_t*)(Qb + swz(((wr + g) << 7) + kb + (q << 2)));
            af[1] = *(const uint32_t*)(Qb + swz(((wr + g + 8) << 7) + kb + (q << 2)));
            af[2] = *(const uint32_t*)(Qb + swz(((wr + g) << 7) + kb + 16 + (q << 2)));
            af[3] = *(const uint32_t*)(Qb + swz(((wr + g + 8) << 7) + kb + 16 + (q << 2)));
#pragma unroll
            for (int nt = 0; nt < 8; nt++) {
                uint32_t bf[2];
                bf[0] = *(const uint32_t*)(Kb + swz((((nt << 3) + g) << 7) + kb + (q << 2)));
                bf[1] = *(const uint32_t*)(Kb + swz((((nt << 3) + g) << 7) + kb + 16 + (q << 2)));
                mma_f16(sacc[nt], af, bf);
            }
        }

        // scale + causal mask (diagonal tile only)
        bool diag = (jt == it);
        float mn0 = -1e30f, mn1 = -1e30f;
#pragma unroll
        for (int nt = 0; nt < 8; nt++) {
#pragma unroll
            for (int j = 0; j < 4; j++) {
                float s = sacc[nt][j] * 0.125f;
                if (diag) {
                    int col = (nt << 3) + (q << 1) + (j & 1);
                    int row = wr + g + ((j >> 1) << 3);
                    if (col > row) s = -1e30f;
                }
                sacc[nt][j] = s;
            }
            mn0 = fmaxf(mn0, fmaxf(sacc[nt][0], sacc[nt][1]));
            mn1 = fmaxf(mn1, fmaxf(sacc[nt][2], sacc[nt][3]));
        }
        mn0 = fmaxf(mn0, __shfl_xor_sync(0xffffffffu, mn0, 1));
        mn0 = fmaxf(mn0, __shfl_xor_sync(0xffffffffu, mn0, 2));
        mn1 = fmaxf(mn1, __shfl_xor_sync(0xffffffffu, mn1, 1));
        mn1 = fmaxf(mn1, __shfl_xor_sync(0xffffffffu, mn1, 2));

        float mnew0 = fmaxf(m0, mn0), mnew1 = fmaxf(m1, mn1);
        float a0 = __expf(m0 - mnew0), a1 = __expf(m1 - mnew1);
        m0 = mnew0; m1 = mnew1;

        float rs0 = 0.f, rs1 = 0.f;
        uint32_t ph[8][2];
#pragma unroll
        for (int nt = 0; nt < 8; nt++) {
            float p0 = __expf(sacc[nt][0] - m0);
            float p1 = __expf(sacc[nt][1] - m0);
            float p2 = __expf(sacc[nt][2] - m1);
            float p3 = __expf(sacc[nt][3] - m1);
            rs0 += p0 + p1; rs1 += p2 + p3;
            ph[nt][0] = packh2(p0, p1);
            ph[nt][1] = packh2(p2, p3);
        }
        rs0 += __shfl_xor_sync(0xffffffffu, rs0, 1);
        rs0 += __shfl_xor_sync(0xffffffffu, rs0, 2);
        rs1 += __shfl_xor_sync(0xffffffffu, rs1, 1);
        rs1 += __shfl_xor_sync(0xffffffffu, rs1, 2);
        l0 = l0 * a0 + rs0;
        l1 = l1 * a1 + rs1;
#pragma unroll
        for (int nt = 0; nt < 8; nt++) {
            oacc[nt][0] *= a0; oacc[nt][1] *= a0;
            oacc[nt][2] *= a1; oacc[nt][3] *= a1;
        }

        // O += P @ V  (B fragments via ldmatrix.trans on key-major V)
        uint32_t vbase = smem_u32(Vs[buf]);
        int t = lane >> 3, r = lane & 7;
#pragma unroll
        for (int s = 0; s < 4; s++) {
            uint32_t pa[4] = { ph[2 * s][0], ph[2 * s][1], ph[2 * s + 1][0], ph[2 * s + 1][1] };
#pragma unroll
            for (int ntp = 0; ntp < 4; ntp++) {
                uint32_t b0, b1, b2, b3;
                uint32_t la = vbase + swz((((s << 4) + ((t & 1) << 3) + r) << 7) +
                                          (((ntp << 1) + (t >> 1)) << 4));
                ldsm_x4_t(b0, b1, b2, b3, la);
                uint32_t bA[2] = { b0, b1 }, bB[2] = { b2, b3 };
                mma_f16(oacc[2 * ntp], pa, bA);
                mma_f16(oacc[2 * ntp + 1], pa, bB);
            }
        }
        __syncthreads();
    }

    // epilogue
    float i0 = 1.f / l0, i1 = 1.f / l1;
    int rowg = b * TT + it * 64 + wr + g;
    __half* O0 = o + (size_t)rowg * CC + h * 64;
    __half* O1 = o + (size_t)(rowg + 8) * CC + h * 64;
#pragma unroll
    for (int nt = 0; nt < 8; nt++) {
        int col = (nt << 3) + (q << 1);
        *(uint32_t*)(O0 + col) = packh2(oacc[nt][0] * i0, oacc[nt][1] * i0);
        *(uint32_t*)(O1 + col) = packh2(oacc[nt][2] * i1, oacc[nt][3] * i1);
    }
}

// ---------------- loss -------------------------------------------------------
__global__ __launch_bounds__(256) void row_loss_kernel(
    const float* __restrict__ logits, const int* __restrict__ targets,
    float* __restrict__ rl)
{
    __shared__ float buf[256];
    int row = blockIdx.x;
    const float* lr = logits + (size_t)row * VV;
    float m = -3.4e38f;
    for (int j = threadIdx.x; j < VV; j += 256) m = fmaxf(m, lr[j]);
    m = block_reduce_max(m, buf);
    float s = 0.f;
    for (int j = threadIdx.x; j < VV; j += 256) s += __expf(lr[j] - m);
    s = block_reduce_sum(s, buf);
    if (threadIdx.x == 0) {
        int t = targets[row];
        rl[row] = -(lr[t] - m - logf(s));
    }
}

__global__ __launch_bounds__(256) void loss_reduce_kernel(
    const float* __restrict__ rl, float* __restrict__ out)
{
    __shared__ float buf[256];
    float s = 0.f;
    for (int i = threadIdx.x; i < NN; i += 256) s += rl[i];
    s = block_reduce_sum(s, buf);
    if (threadIdx.x == 0) out[0] = s * (1.f / NN);
}

// ---------------- host orchestration ----------------------------------------
static inline void run_gemm(const __half* A, const __half* Wt, const float* bias,
                            const float* res, float* C, __half* Ch,
                            int M, int N, int K, int relu)
{
    int grid = (M / 128) * (N / 128);
    mma_gemm_kernel<<<grid, 256, GEMM_SMEM>>>(A, Wt, bias, res, C, Ch, M, N, K, relu);
}

extern "C" void kernel_launch(void* const* d_in, const int* in_sizes, int n_in,
                              void* d_out, int out_size)
{
    const int*   idx     = (const int*)  d_in[0];
    const int*   targets = (const int*)  d_in[1];
    const float* tok     = (const float*)d_in[2];
    const float* pos     = (const float*)d_in[3];
    const float* ln1_g   = (const float*)d_in[4];
    const float* ln1_b   = (const float*)d_in[5];
    const float* Wq      = (const float*)d_in[6];
    const float* Wk      = (const float*)d_in[7];
    const float* Wv      = (const float*)d_in[8];
    const float* Wo      = (const float*)d_in[9];
    const float* bo      = (const float*)d_in[10];
    const float* ln2_g   = (const float*)d_in[11];
    const float* ln2_b   = (const float*)d_in[12];
    const float* W1      = (const float*)d_in[13];
    const float* b1      = (const float*)d_in[14];
    const float* W2      = (const float*)d_in[15];
    const float* b2      = (const float*)d_in[16];
    const float* lnf_g   = (const float*)d_in[17];
    const float* lnf_b   = (const float*)d_in[18];
    const float* Wlm     = (const float*)d_in[19];
    const float* blm     = (const float*)d_in[20];
    (void)in_sizes; (void)n_in;

    cudaFuncSetAttribute(mma_gemm_kernel,
                         cudaFuncAttributeMaxDynamicSharedMemorySize, GEMM_SMEM);

    void* p;
    cudaGetSymbolAddress(&p, g_x);      float*  x    = (float*)p;
    cudaGetSymbolAddress(&p, g_h);      __half* h    = (__half*)p;
    cudaGetSymbolAddress(&p, g_qkv);    __half* qkv  = (__half*)p;
    cudaGetSymbolAddress(&p, g_att);    __half* att  = (__half*)p;
    cudaGetSymbolAddress(&p, g_ffh);    __half* ffh  = (__half*)p;
    cudaGetSymbolAddress(&p, g_rowloss);float*  rl   = (float*)p;
    cudaGetSymbolAddress(&p, g_logits_fb); float* logits_fb = (float*)p;
    cudaGetSymbolAddress(&p, g_WqkvT);  __half* WqkvT = (__half*)p;
    cudaGetSymbolAddress(&p, g_WoT);    __half* WoT  = (__half*)p;
    cudaGetSymbolAddress(&p, g_W1T);    __half* W1T  = (__half*)p;
    cudaGetSymbolAddress(&p, g_W2T);    __half* W2T  = (__half*)p;
    cudaGetSymbolAddress(&p, g_WlmT);   __half* WlmT = (__half*)p;

    const size_t NV = (size_t)NN * VV;
    float* out = (float*)d_out;
    bool big = ((size_t)out_size >= NV);
    float* logits   = big ? out : logits_fb;
    float* loss_dst = ((size_t)out_size > NV) ? out + NV
                    : (big ? rl + NN : out);

    // transpose all weights to fp16 [N,K]; QKV packed as [3C,K]
    transpose_kernel<<<dim3(CC/32, CC/32, LL), 256>>>(Wq, WqkvT + 0 * (size_t)CC * CC,
        CC, CC, (size_t)CC * CC, (size_t)C3 * CC);
    transpose_kernel<<<dim3(CC/32, CC/32, LL), 256>>>(Wk, WqkvT + 1 * (size_t)CC * CC,
        CC, CC, (size_t)CC * CC, (size_t)C3 * CC);
    transpose_kernel<<<dim3(CC/32, CC/32, LL), 256>>>(Wv, WqkvT + 2 * (size_t)CC * CC,
        CC, CC, (size_t)CC * CC, (size_t)C3 * CC);
    transpose_kernel<<<dim3(CC/32, CC/32, LL), 256>>>(Wo, WoT, CC, CC,
        (size_t)CC * CC, (size_t)CC * CC);
    transpose_kernel<<<dim3(FF/32, CC/32, LL), 256>>>(W1, W1T, CC, FF,
        (size_t)CC * FF, (size_t)CC * FF);
    transpose_kernel<<<dim3(CC/32, FF/32, LL), 256>>>(W2, W2T, FF, CC,
        (size_t)FF * CC, (size_t)FF * CC);
    transpose_kernel<<<dim3(VV/32, CC/32, 1),  256>>>(Wlm, WlmT, CC, VV, 0, 0);

    // embedding
    embed_kernel<<<(NN * CC) / 256, 256>>>(idx, tok, pos, x);

    for (int l = 0; l < LL; l++) {
        const size_t oC  = (size_t)l * CC;
        const size_t oCC = (size_t)l * CC * CC;
        const size_t oCF = (size_t)l * CC * FF;
        const size_t oF  = (size_t)l * FF;
        const size_t oQ  = (size_t)l * C3 * CC;

        ln_kernel<<<NN, 256>>>(x, ln1_g + oC, ln1_b + oC, h);
        run_gemm(h, WqkvT + oQ, nullptr, nullptr, nullptr, qkv, NN, C3, CC, 0);

        flash_attn<<<dim3(TT / 64, BB * HH), 128>>>(qkv, att);

        run_gemm(att, WoT + oCC, bo + oC, x, x, nullptr, NN, CC, CC, 0);

        ln_kernel<<<NN, 256>>>(x, ln2_g + oC, ln2_b + oC, h);
        run_gemm(h, W1T + oCF, b1 + oF, nullptr, nullptr, ffh, NN, FF, CC, 1);
        run_gemm(ffh, W2T + oCF, b2 + oC, x, x, nullptr, NN, CC, FF, 0);
    }

    ln_kernel<<<NN, 256>>>(x, lnf_g, lnf_b, h);
    run_gemm(h, WlmT, blm, nullptr, logits, nullptr, NN, VV, CC, 0);

    row_loss_kernel<<<NN, 256>>>(logits, targets, rl);
    loss_reduce_kernel<<<1, 256>>>(rl, loss_dst);
}

// round 8
// speedup vs baseline: 3.2284x; 1.0408x over previous
#include <cuda_runtime.h>
#include <cuda_fp16.h>
#include <cstdint>

// Problem constants
#define BB 4
#define TT 1024
#define CC 1024
#define HH 16
#define HS 64
#define LL 12
#define VV 50304
#define NN (BB*TT)          // 4096 tokens
#define FF (4*CC)           // 4096
#define C3 (3*CC)           // 3072

// ---------------- scratch (device globals; no allocation allowed) -----------
__device__ float  g_x[NN*CC];
__device__ __half g_h[NN*CC];
__device__ __half g_qkv[(size_t)NN*C3];
__device__ __half g_att[NN*CC];
__device__ __half g_ffh[(size_t)NN*FF];
__device__ float  g_rowloss[NN + 4];
__device__ float  g_logits_fb[(size_t)NN*VV];    // fallback if d_out too small
// transposed weights [N,K] (fp16)
__device__ __half g_WqkvT[(size_t)LL*C3*CC];     // rows: [Wq; Wk; Wv]
__device__ __half g_WoT[(size_t)LL*CC*CC];
__device__ __half g_W1T[(size_t)LL*CC*FF];
__device__ __half g_W2T[(size_t)LL*FF*CC];
__device__ __half g_WlmT[(size_t)CC*VV];

// ---------------- helpers ----------------------------------------------------
__device__ __forceinline__ uint32_t smem_u32(const void* p) {
    uint32_t a;
    asm("{ .reg .u64 t; cvta.to.shared.u64 t, %1; cvt.u32.u64 %0, t; }" : "=r"(a) : "l"(p));
    return a;
}
__device__ __forceinline__ uint32_t swz(uint32_t b) { return b ^ ((b >> 3) & 0x70); }

__device__ __forceinline__ void cp16(void* s, const void* g) {
    uint32_t sa = smem_u32(s);
    asm volatile("cp.async.cg.shared.global [%0], [%1], 16;" :: "r"(sa), "l"(g));
}
#define CP_COMMIT() asm volatile("cp.async.commit_group;" ::: "memory")
#define CP_WAIT(n)  asm volatile("cp.async.wait_group %0;" :: "n"(n) : "memory")

__device__ __forceinline__ void mma_f16(float* d, const uint32_t* a, const uint32_t* b) {
    asm volatile(
        "mma.sync.aligned.m16n8k16.row.col.f32.f16.f16.f32 "
        "{%0,%1,%2,%3}, {%4,%5,%6,%7}, {%8,%9}, {%0,%1,%2,%3};"
        : "+f"(d[0]), "+f"(d[1]), "+f"(d[2]), "+f"(d[3])
        : "r"(a[0]), "r"(a[1]), "r"(a[2]), "r"(a[3]), "r"(b[0]), "r"(b[1]));
}
__device__ __forceinline__ void ldsm_x4_t(uint32_t& r0, uint32_t& r1,
                                          uint32_t& r2, uint32_t& r3, uint32_t addr) {
    asm volatile("ldmatrix.sync.aligned.m8n8.x4.trans.shared.b16 {%0,%1,%2,%3}, [%4];"
        : "=r"(r0), "=r"(r1), "=r"(r2), "=r"(r3) : "r"(addr));
}
__device__ __forceinline__ uint32_t packh2(float a, float b) {
    __half2 h = __floats2half2_rn(a, b);
    return *(uint32_t*)&h;
}

// ---------------- reductions ------------------------------------------------
__device__ __forceinline__ float block_reduce_sum(float v, float* buf) {
    int tid = threadIdx.x;
    buf[tid] = v; __syncthreads();
    for (int s = 128; s > 0; s >>= 1) {
        if (tid < s) buf[tid] += buf[tid + s];
        __syncthreads();
    }
    float r = buf[0]; __syncthreads();
    return r;
}
__device__ __forceinline__ float block_reduce_max(float v, float* buf) {
    int tid = threadIdx.x;
    buf[tid] = v; __syncthreads();
    for (int s = 128; s > 0; s >>= 1) {
        if (tid < s) buf[tid] = fmaxf(buf[tid], buf[tid + s]);
        __syncthreads();
    }
    float r = buf[0]; __syncthreads();
    return r;
}

// ---------------- transpose: dst[N,K] = half(src[K,N]), 64x64 tiles ----------
__global__ __launch_bounds__(256) void transpose_kernel(
    const float* __restrict__ src, __half* __restrict__ dst, int K, int N,
    size_t src_zstride, size_t dst_zstride)
{
    __shared__ float t[64][65];
    const float* s = src + (size_t)blockIdx.z * src_zstride;
    __half* d = dst + (size_t)blockIdx.z * dst_zstride;
    int n0 = blockIdx.x << 6, k0 = blockIdx.y << 6;
    int tid = threadIdx.x;
    // read: 64 k-rows x 64 n-cols, float4 along n
    int r = tid >> 4, c4 = (tid & 15) << 2;
#pragma unroll
    for (int p = 0; p < 4; p++) {
        float4 v = *(const float4*)(s + (size_t)(k0 + r + p * 16) * N + n0 + c4);
        t[r + p * 16][c4 + 0] = v.x; t[r + p * 16][c4 + 1] = v.y;
        t[r + p * 16][c4 + 2] = v.z; t[r + p * 16][c4 + 3] = v.w;
    }
    __syncthreads();
    // write: warp w handles n-rows w, w+8, ...; lane covers k via half2 (128B/warp)
    int lane = tid & 31, w = tid >> 5;
#pragma unroll
    for (int p = 0; p < 8; p++) {
        int n = w + (p << 3);
        int k = lane << 1;
        *(uint32_t*)(d + (size_t)(n0 + n) * K + k0 + k) =
            packh2(t[k][n], t[k + 1][n]);
    }
}

// ---------------- embedding (float4) -----------------------------------------
__global__ __launch_bounds__(256) void embed_kernel(
    const int* __restrict__ idx, const float* __restrict__ tok,
    const float* __restrict__ pos, float* __restrict__ x)
{
    size_t i4 = (size_t)blockIdx.x * 256 + threadIdx.x;   // over NN*CC/4
    int n = (int)(i4 >> 8);
    int c = (int)(i4 & 255) << 2;
    int t = n & (TT - 1);
    float4 tv = *(const float4*)(tok + (size_t)idx[n] * CC + c);
    float4 pv = *(const float4*)(pos + (size_t)t * CC + c);
    float4 o; o.x = tv.x + pv.x; o.y = tv.y + pv.y; o.z = tv.z + pv.z; o.w = tv.w + pv.w;
    *(float4*)(x + (size_t)n * CC + c) = o;
}

// ---------------- layernorm (float4 in, fp16 out) ----------------------------
__global__ __launch_bounds__(256) void ln_kernel(
    const float* __restrict__ x, const float* __restrict__ g,
    const float* __restrict__ b, __half* __restrict__ out)
{
    __shared__ float buf[256];
    int row = blockIdx.x;
    int c = threadIdx.x << 2;
    const float* xr = x + (size_t)row * CC;
    float4 v = *(const float4*)(xr + c);
    float s  = v.x + v.y + v.z + v.w;
    float ss = v.x * v.x + v.y * v.y + v.z * v.z + v.w * v.w;
    s  = block_reduce_sum(s, buf);
    ss = block_reduce_sum(ss, buf);
    float mu  = s * (1.f / CC);
    float inv = rsqrtf(ss * (1.f / CC) - mu * mu + 1e-5f);
    float4 gv = *(const float4*)(g + c);
    float4 bv = *(const float4*)(b + c);
    uint32_t o0 = packh2((v.x - mu) * inv * gv.x + bv.x, (v.y - mu) * inv * gv.y + bv.y);
    uint32_t o1 = packh2((v.z - mu) * inv * gv.z + bv.z, (v.w - mu) * inv * gv.w + bv.w);
    uint2 o; o.x = o0; o.y = o1;
    *(uint2*)(out + (size_t)row * CC + c) = o;
}

// ---------------- mma.sync fp16 GEMM: C = A[M,K] @ Bt[N,K]^T -----------------
// BM=128, BN=128, BK=64, 256 threads (8 warps, 2x4), 3-stage cp.async pipeline.
// Full register budget: register-limited to 1 CTA/SM — do NOT cap regs.
#define GEMM_SMEM (3*32768)
#define GW 16
__global__ __launch_bounds__(256) void mma_gemm_kernel(
    const __half* __restrict__ A, const __half* __restrict__ Bt,
    const float* __restrict__ bias, const float* __restrict__ res,
    float* __restrict__ C, __half* __restrict__ Ch,
    int M, int N, int K, int relu)
{
    extern __shared__ char smem[];
    int tid = threadIdx.x;
    int wid = tid >> 5, lane = tid & 31;
    int g = lane >> 2, q = lane & 3;
    int wm0 = (wid >> 2) << 6;
    int wn0 = (wid & 3) << 5;

    int Mb = M >> 7, Nb = N >> 7;
    int bid = blockIdx.x;
    int group = bid / (Mb * GW);
    int rem = bid - group * Mb * GW;
    int gw = Nb - group * GW; if (gw > GW) gw = GW;
    int n_blk = group * GW + rem % gw;
    int m_blk = rem / gw;
    int m0 = m_blk << 7, n0 = n_blk << 7;

    const __half* Abase = A + (size_t)m0 * K;
    const __half* Bbase = Bt + (size_t)n0 * K;
    int Kc = K >> 6;

    float acc[4][4][4] = {};

#pragma unroll
    for (int c = 0; c < 2; c++) {
        char* sa = smem + c * 32768;
        char* sbm = sa + 16384;
#pragma unroll
        for (int p = 0; p < 4; p++) {
            int id = p * 256 + tid;
            int row = id >> 3, ch = id & 7;
            uint32_t off = swz((row << 7) + (ch << 4));
            cp16(sa + off, Abase + (size_t)row * K + (c << 6) + (ch << 3));
            cp16(sbm + off, Bbase + (size_t)row * K + (c << 6) + (ch << 3));
        }
        CP_COMMIT();
    }

    for (int c = 0; c < Kc; c++) {
        if (c + 2 < Kc) { CP_WAIT(1); } else { CP_WAIT(0); }
        __syncthreads();
        if (c + 2 < Kc) {
            int cs = c + 2;
            char* sa = smem + (cs % 3) * 32768;
            char* sbm = sa + 16384;
#pragma unroll
            for (int p = 0; p < 4; p++) {
                int id = p * 256 + tid;
                int row = id >> 3, ch = id & 7;
                uint32_t off = swz((row << 7) + (ch << 4));
                cp16(sa + off, Abase + (size_t)row * K + (cs << 6) + (ch << 3));
                cp16(sbm + off, Bbase + (size_t)row * K + (cs << 6) + (ch << 3));
            }
            CP_COMMIT();
        }
        const char* As = smem + (c % 3) * 32768;
        const char* Bs = As + 16384;
#pragma unroll
        for (int ks = 0; ks < 4; ks++) {
            int kb = ks << 5;
            uint32_t af[4][4];
#pragma unroll
            for (int mi = 0; mi < 4; mi++) {
                int r = wm0 + (mi << 4) + g;
                af[mi][0] = *(const uint32_t*)(As + swz((r << 7) + kb + (q << 2)));
                af[mi][1] = *(const uint32_t*)(As + swz(((r + 8) << 7) + kb + (q << 2)));
                af[mi][2] = *(const uint32_t*)(As + swz((r << 7) + kb + 16 + (q << 2)));
                af[mi][3] = *(const uint32_t*)(As + swz(((r + 8) << 7) + kb + 16 + (q << 2)));
            }
            uint32_t bf[4][2];
#pragma unroll
            for (int ni = 0; ni < 4; ni++) {
                int n = wn0 + (ni << 3) + g;
                bf[ni][0] = *(const uint32_t*)(Bs + swz((n << 7) + kb + (q << 2)));
                bf[ni][1] = *(const uint32_t*)(Bs + swz((n << 7) + kb + 16 + (q << 2)));
            }
#pragma unroll
            for (int mi = 0; mi < 4; mi++)
#pragma unroll
                for (int ni = 0; ni < 4; ni++)
                    mma_f16(acc[mi][ni], af[mi], bf[ni]);
        }
    }

#pragma unroll
    for (int mi = 0; mi < 4; mi++) {
#pragma unroll
        for (int half = 0; half < 2; half++) {
            int row = m0 + wm0 + (mi << 4) + g + half * 8;
            const float* rrow = res ? res + (size_t)row * N : nullptr;
#pragma unroll
            for (int ni = 0; ni < 4; ni++) {
                int col = n0 + wn0 + (ni << 3) + (q << 1);
                float v0 = acc[mi][ni][half * 2 + 0];
                float v1 = acc[mi][ni][half * 2 + 1];
                if (bias) { v0 += bias[col]; v1 += bias[col + 1]; }
                if (relu) { v0 = fmaxf(v0, 0.f); v1 = fmaxf(v1, 0.f); }
                if (rrow) { v0 += rrow[col]; v1 += rrow[col + 1]; }
                if (Ch) {
                    *(uint32_t*)(Ch + (size_t)row * N + col) = packh2(v0, v1);
                } else {
                    float2 o; o.x = v0; o.y = v1;
                    *(float2*)(C + (size_t)row * N + col) = o;
                }
            }
        }
    }
}

// ---------------- fused flash attention --------------------------------------
__global__ __launch_bounds__(128) void flash_attn(
    const __half* __restrict__ qkv, __half* __restrict__ o)
{
    __shared__ __align__(16) __half Qs[64 * 64];
    __shared__ __align__(16) __half Ks[2][64 * 64];
    __shared__ __align__(16) __half Vs[2][64 * 64];

    int it = (int)gridDim.x - 1 - (int)blockIdx.x;   // longest tiles first
    int bh = blockIdx.y;
    int b = bh >> 4, h = bh & 15;
    int tid = threadIdx.x;
    int wid = tid >> 5, lane = tid & 31;
    int g = lane >> 2, q = lane & 3;
    int wr = wid << 4;

    const __half* Qg = qkv + ((size_t)b * TT + (size_t)it * 64) * C3 + h * 64;

#pragma unroll
    for (int p = 0; p < 4; p++) {
        int id = p * 128 + tid;
        int row = id >> 3, ch = id & 7;
        cp16((char*)Qs + swz((row << 7) + (ch << 4)), Qg + (size_t)row * C3 + (ch << 3));
    }
    CP_COMMIT();

    {
        const __half* Kg = qkv + (size_t)b * TT * C3 + CC + h * 64;
        const __half* Vg = qkv + (size_t)b * TT * C3 + 2 * CC + h * 64;
#pragma unroll
        for (int p = 0; p < 4; p++) {
            int id = p * 128 + tid;
            int row = id >> 3, ch = id & 7;
            uint32_t off = swz((row << 7) + (ch << 4));
            cp16((char*)Ks[0] + off, Kg + (size_t)row * C3 + (ch << 3));
            cp16((char*)Vs[0] + off, Vg + (size_t)row * C3 + (ch << 3));
        }
        CP_COMMIT();
    }

    float m0 = -1e30f, m1 = -1e30f;
    float l0 = 0.f, l1 = 0.f;
    float oacc[8][4] = {};

    for (int jt = 0; jt <= it; jt++) {
        int buf = jt & 1;
        if (jt < it) {
            int nb = (jt + 1) & 1;
            const __half* Kg = qkv + ((size_t)b * TT + (size_t)(jt + 1) * 64) * C3 + CC + h * 64;
            const __half* Vg = qkv + ((size_t)b * TT + (size_t)(jt + 1) * 64) * C3 + 2 * CC + h * 64;
#pragma unroll
            for (int p = 0; p < 4; p++) {
                int id = p * 128 + tid;
                int row = id >> 3, ch = id & 7;
                uint32_t off = swz((row << 7) + (ch << 4));
                cp16((char*)Ks[nb] + off, Kg + (size_t)row * C3 + (ch << 3));
                cp16((char*)Vs[nb] + off, Vg + (size_t)row * C3 + (ch << 3));
            }
            CP_COMMIT();
            CP_WAIT(1);
        } else {
            CP_WAIT(0);
        }
        __syncthreads();

        float sacc[8][4] = {};
        const char* Qb = (const char*)Qs;
        const char* Kb = (const char*)Ks[buf];
#pragma unroll
        for (int ks = 0; ks < 4; ks++) {
            int kb = ks << 5;
            uint32_t af[4];
            af[0] = *(const uint32_t*)(Qb + swz(((wr + g) << 7) + kb + (q << 2)));
            af[1] = *(const uint32_t*)(Qb + swz(((wr + g + 8) << 7) + kb + (q << 2)));
            af[2] = *(const uint32_t*)(Qb + swz(((wr + g) << 7) + kb + 16 + (q << 2)));
            af[3] = *(const uint32_t*)(Qb + swz(((wr + g + 8) << 7) + kb + 16 + (q << 2)));
#pragma unroll
            for (int nt = 0; nt < 8; nt++) {
                uint32_t bf[2];
                bf[0] = *(const uint32_t*)(Kb + swz((((nt << 3) + g) << 7) + kb + (q << 2)));
                bf[1] = *(const uint32_t*)(Kb + swz((((nt << 3) + g) << 7) + kb + 16 + (q << 2)));
                mma_f16(sacc[nt], af, bf);
            }
        }

        bool diag = (jt == it);
        float mn0 = -1e30f, mn1 = -1e30f;
#pragma unroll
        for (int nt = 0; nt < 8; nt++) {
#pragma unroll
            for (int j = 0; j < 4; j++) {
                float s = sacc[nt][j] * 0.125f;
                if (diag) {
                    int col = (nt << 3) + (q << 1) + (j & 1);
                    int row = wr + g + ((j >> 1) << 3);
                    if (col > row) s = -1e30f;
                }
                sacc[nt][j] = s;
            }
            mn0 = fmaxf(mn0, fmaxf(sacc[nt][0], sacc[nt][1]));
            mn1 = fmaxf(mn1, fmaxf(sacc[nt][2], sacc[nt][3]));
        }
        mn0 = fmaxf(mn0, __shfl_xor_sync(0xffffffffu, mn0, 1));
        mn0 = fmaxf(mn0, __shfl_xor_sync(0xffffffffu, mn0, 2));
        mn1 = fmaxf(mn1, __shfl_xor_sync(0xffffffffu, mn1, 1));
        mn1 = fmaxf(mn1, __shfl_xor_sync(0xffffffffu, mn1, 2));

        float mnew0 = fmaxf(m0, mn0), mnew1 = fmaxf(m1, mn1);
        float a0 = __expf(m0 - mnew0), a1 = __expf(m1 - mnew1);
        m0 = mnew0; m1 = mnew1;

        float rs0 = 0.f, rs1 = 0.f;
        uint32_t ph[8][2];
#pragma unroll
        for (int nt = 0; nt < 8; nt++) {
            float p0 = __expf(sacc[nt][0] - m0);
            float p1 = __expf(sacc[nt][1] - m0);
            float p2 = __expf(sacc[nt][2] - m1);
            float p3 = __expf(sacc[nt][3] - m1);
            rs0 += p0 + p1; rs1 += p2 + p3;
            ph[nt][0] = packh2(p0, p1);
            ph[nt][1] = packh2(p2, p3);
        }
        rs0 += __shfl_xor_sync(0xffffffffu, rs0, 1);
        rs0 += __shfl_xor_sync(0xffffffffu, rs0, 2);
        rs1 += __shfl_xor_sync(0xffffffffu, rs1, 1);
        rs1 += __shfl_xor_sync(0xffffffffu, rs1, 2);
        l0 = l0 * a0 + rs0;
        l1 = l1 * a1 + rs1;
#pragma unroll
        for (int nt = 0; nt < 8; nt++) {
            oacc[nt][0] *= a0; oacc[nt][1] *= a0;
            oacc[nt][2] *= a1; oacc[nt][3] *= a1;
        }

        uint32_t vbase = smem_u32(Vs[buf]);
        int t = lane >> 3, r = lane & 7;
#pragma unroll
        for (int s = 0; s < 4; s++) {
            uint32_t pa[4] = { ph[2 * s][0], ph[2 * s][1], ph[2 * s + 1][0], ph[2 * s + 1][1] };
#pragma unroll
            for (int ntp = 0; ntp < 4; ntp++) {
                uint32_t b0, b1, b2, b3;
                uint32_t la = vbase + swz((((s << 4) + ((t & 1) << 3) + r) << 7) +
                                          (((ntp << 1) + (t >> 1)) << 4));
                ldsm_x4_t(b0, b1, b2, b3, la);
                uint32_t bA[2] = { b0, b1 }, bB[2] = { b2, b3 };
                mma_f16(oacc[2 * ntp], pa, bA);
                mma_f16(oacc[2 * ntp + 1], pa, bB);
            }
        }
        __syncthreads();
    }

    float i0 = 1.f / l0, i1 = 1.f / l1;
    int rowg = b * TT + it * 64 + wr + g;
    __half* O0 = o + (size_t)rowg * CC + h * 64;
    __half* O1 = o + (size_t)(rowg + 8) * CC + h * 64;
#pragma unroll
    for (int nt = 0; nt < 8; nt++) {
        int col = (nt << 3) + (q << 1);
        *(uint32_t*)(O0 + col) = packh2(oacc[nt][0] * i0, oacc[nt][1] * i0);
        *(uint32_t*)(O1 + col) = packh2(oacc[nt][2] * i1, oacc[nt][3] * i1);
    }
}

// ---------------- loss: single-pass online logsumexp --------------------------
__global__ __launch_bounds__(256) void row_loss_kernel(
    const float* __restrict__ logits, const int* __restrict__ targets,
    float* __restrict__ rl)
{
    __shared__ float buf[256];
    int row = blockIdx.x;
    const float* lr = logits + (size_t)row * VV;
    float m = -3.4e38f, s = 0.f;
    // VV = 50304 = 12576 float4
    for (int j = threadIdx.x; j < 12576; j += 256) {
        float4 v = *(const float4*)(lr + (j << 2));
        float vm = fmaxf(fmaxf(v.x, v.y), fmaxf(v.z, v.w));
        if (vm > m) { s *= __expf(m - vm); m = vm; }
        s += __expf(v.x - m) + __expf(v.y - m) + __expf(v.z - m) + __expf(v.w - m);
    }
    float gm = block_reduce_max(m, buf);
    s = block_reduce_sum(s * __expf(m - gm), buf);
    if (threadIdx.x == 0) {
        int t = targets[row];
        rl[row] = -(lr[t] - gm - logf(s));
    }
}

__global__ __launch_bounds__(256) void loss_reduce_kernel(
    const float* __restrict__ rl, float* __restrict__ out)
{
    __shared__ float buf[256];
    float s = 0.f;
    for (int i = threadIdx.x; i < NN; i += 256) s += rl[i];
    s = block_reduce_sum(s, buf);
    if (threadIdx.x == 0) out[0] = s * (1.f / NN);
}

// ---------------- host orchestration ----------------------------------------
static inline void run_gemm(const __half* A, const __half* Wt, const float* bias,
                            const float* res, float* C, __half* Ch,
                            int M, int N, int K, int relu)
{
    int grid = (M / 128) * (N / 128);
    mma_gemm_kernel<<<grid, 256, GEMM_SMEM>>>(A, Wt, bias, res, C, Ch, M, N, K, relu);
}

extern "C" void kernel_launch(void* const* d_in, const int* in_sizes, int n_in,
                              void* d_out, int out_size)
{
    const int*   idx     = (const int*)  d_in[0];
    const int*   targets = (const int*)  d_in[1];
    const float* tok     = (const float*)d_in[2];
    const float* pos     = (const float*)d_in[3];
    const float* ln1_g   = (const float*)d_in[4];
    const float* ln1_b   = (const float*)d_in[5];
    const float* Wq      = (const float*)d_in[6];
    const float* Wk      = (const float*)d_in[7];
    const float* Wv      = (const float*)d_in[8];
    const float* Wo      = (const float*)d_in[9];
    const float* bo      = (const float*)d_in[10];
    const float* ln2_g   = (const float*)d_in[11];
    const float* ln2_b   = (const float*)d_in[12];
    const float* W1      = (const float*)d_in[13];
    const float* b1      = (const float*)d_in[14];
    const float* W2      = (const float*)d_in[15];
    const float* b2      = (const float*)d_in[16];
    const float* lnf_g   = (const float*)d_in[17];
    const float* lnf_b   = (const float*)d_in[18];
    const float* Wlm     = (const float*)d_in[19];
    const float* blm     = (const float*)d_in[20];
    (void)in_sizes; (void)n_in;

    cudaFuncSetAttribute(mma_gemm_kernel,
                         cudaFuncAttributeMaxDynamicSharedMemorySize, GEMM_SMEM);

    void* p;
    cudaGetSymbolAddress(&p, g_x);      float*  x    = (float*)p;
    cudaGetSymbolAddress(&p, g_h);      __half* h    = (__half*)p;
    cudaGetSymbolAddress(&p, g_qkv);    __half* qkv  = (__half*)p;
    cudaGetSymbolAddress(&p, g_att);    __half* att  = (__half*)p;
    cudaGetSymbolAddress(&p, g_ffh);    __half* ffh  = (__half*)p;
    cudaGetSymbolAddress(&p, g_rowloss);float*  rl   = (float*)p;
    cudaGetSymbolAddress(&p, g_logits_fb); float* logits_fb = (float*)p;
    cudaGetSymbolAddress(&p, g_WqkvT);  __half* WqkvT = (__half*)p;
    cudaGetSymbolAddress(&p, g_WoT);    __half* WoT  = (__half*)p;
    cudaGetSymbolAddress(&p, g_W1T);    __half* W1T  = (__half*)p;
    cudaGetSymbolAddress(&p, g_W2T);    __half* W2T  = (__half*)p;
    cudaGetSymbolAddress(&p, g_WlmT);   __half* WlmT = (__half*)p;

    const size_t NV = (size_t)NN * VV;
    float* out = (float*)d_out;
    bool big = ((size_t)out_size >= NV);
    float* logits   = big ? out : logits_fb;
    float* loss_dst = ((size_t)out_size > NV) ? out + NV
                    : (big ? rl + NN : out);

    // transpose all weights to fp16 [N,K]; QKV packed as [3C,K] (64x64 tiles)
    transpose_kernel<<<dim3(CC/64, CC/64, LL), 256>>>(Wq, WqkvT + 0 * (size_t)CC * CC,
        CC, CC, (size_t)CC * CC, (size_t)C3 * CC);
    transpose_kernel<<<dim3(CC/64, CC/64, LL), 256>>>(Wk, WqkvT + 1 * (size_t)CC * CC,
        CC, CC, (size_t)CC * CC, (size_t)C3 * CC);
    transpose_kernel<<<dim3(CC/64, CC/64, LL), 256>>>(Wv, WqkvT + 2 * (size_t)CC * CC,
        CC, CC, (size_t)CC * CC, (size_t)C3 * CC);
    transpose_kernel<<<dim3(CC/64, CC/64, LL), 256>>>(Wo, WoT, CC, CC,
        (size_t)CC * CC, (size_t)CC * CC);
    transpose_kernel<<<dim3(FF/64, CC/64, LL), 256>>>(W1, W1T, CC, FF,
        (size_t)CC * FF, (size_t)CC * FF);
    transpose_kernel<<<dim3(CC/64, FF/64, LL), 256>>>(W2, W2T, FF, CC,
        (size_t)FF * CC, (size_t)FF * CC);
    transpose_kernel<<<dim3(VV/64, CC/64, 1),  256>>>(Wlm, WlmT, CC, VV, 0, 0);

    // embedding
    embed_kernel<<<(NN * CC / 4) / 256, 256>>>(idx, tok, pos, x);

    for (int l = 0; l < LL; l++) {
        const size_t oC  = (size_t)l * CC;
        const size_t oCC = (size_t)l * CC * CC;
        const size_t oCF = (size_t)l * CC * FF;
        const size_t oF  = (size_t)l * FF;
        const size_t oQ  = (size_t)l * C3 * CC;

        ln_kernel<<<NN, 256>>>(x, ln1_g + oC, ln1_b + oC, h);
        run_gemm(h, WqkvT + oQ, nullptr, nullptr, nullptr, qkv, NN, C3, CC, 0);

        flash_attn<<<dim3(TT / 64, BB * HH), 128>>>(qkv, att);

        run_gemm(att, WoT + oCC, bo + oC, x, x, nullptr, NN, CC, CC, 0);

        ln_kernel<<<NN, 256>>>(x, ln2_g + oC, ln2_b + oC, h);
        run_gemm(h, W1T + oCF, b1 + oF, nullptr, nullptr, ffh, NN, FF, CC, 1);
        run_gemm(ffh, W2T + oCF, b2 + oC, x, x, nullptr, NN, CC, FF, 0);
    }

    ln_kernel<<<NN, 256>>>(x, lnf_g, lnf_b, h);
    run_gemm(h, WlmT, blm, nullptr, logits, nullptr, NN, VV, CC, 0);

    row_loss_kernel<<<NN, 256>>>(logits, targets, rl);
    loss_reduce_kernel<<<1, 256>>>(rl, loss_dst);
}